// round 11
// baseline (speedup 1.0000x reference)
#include <cuda_runtime.h>
#include <cuda_fp16.h>
#include <math.h>
#include <stdint.h>

// Problem constants (B=4, T=4096, H=512, E=8, K=2, F=2048, cap=5120)
#define NTOK 16384
#define HDIM 512
#define NEXP 8
#define FDIM 2048
#define CAP  5120
#define NK   32768

// ---------------- persistent device scratch (device-side refs ONLY) -----------
__device__ int   g_eidx[NK];
__device__ float g_wgt[NK];
__device__ int   g_slot[NK];
__device__ int   g_s2t[NEXP * CAP];
__device__ int   g_cnt[NEXP];
__device__ __align__(256) __half g_zero[128];

__device__ __align__(256) __half g_xhi[(size_t)NTOK * HDIM];
__device__ __align__(256) __half g_xlo[(size_t)NTOK * HDIM];
__device__ __align__(256) __half g_w1t_hi[(size_t)NEXP * FDIM * HDIM]; // [e][f][h]
__device__ __align__(256) __half g_w2t_hi[(size_t)NEXP * HDIM * FDIM]; // [e][h][f]
__device__ __align__(256) __half g_hhi[(size_t)NEXP * CAP * FDIM];
__device__ __align__(256) __half g_hlo[(size_t)NEXP * CAP * FDIM];
__device__ __align__(256) float g_eo[(size_t)NEXP * CAP * HDIM];

// ---------------- PTX helpers (portable sm_80+) -------------------------------
__device__ __forceinline__ uint32_t smem_u32(const void* p) {
    uint32_t a;
    asm("{ .reg .u64 t; cvta.to.shared.u64 t, %1; cvt.u32.u64 %0, t; }"
        : "=r"(a) : "l"(p));
    return a;
}
__device__ __forceinline__ void cp16(uint32_t dst, const void* src) {
    asm volatile("cp.async.cg.shared.global [%0], [%1], 16;"
                 :: "r"(dst), "l"(src) : "memory");
}
#define CP_COMMIT() asm volatile("cp.async.commit_group;" ::: "memory")
#define CP_WAIT(n)  asm volatile("cp.async.wait_group %0;" :: "n"(n) : "memory")

__device__ __forceinline__ void ldsm4(uint32_t r[4], uint32_t addr) {
    asm volatile("ldmatrix.sync.aligned.m8n8.x4.shared.b16 {%0,%1,%2,%3}, [%4];"
                 : "=r"(r[0]), "=r"(r[1]), "=r"(r[2]), "=r"(r[3]) : "r"(addr));
}
__device__ __forceinline__ void mma16816(float c[4], const uint32_t a[4],
                                         const uint32_t b[2]) {
    asm volatile(
        "mma.sync.aligned.m16n8k16.row.col.f32.f16.f16.f32 "
        "{%0,%1,%2,%3},{%4,%5,%6,%7},{%8,%9},{%0,%1,%2,%3};"
        : "+f"(c[0]), "+f"(c[1]), "+f"(c[2]), "+f"(c[3])
        : "r"(a[0]), "r"(a[1]), "r"(a[2]), "r"(a[3]), "r"(b[0]), "r"(b[1]));
}

// ---------------- 1) router ---------------------------------------------------
__global__ void router_kernel(const float* __restrict__ x,
                              const float* __restrict__ rw) {
    __shared__ float srw[HDIM * NEXP];
    const int tid = threadIdx.x;
    for (int i = tid; i < HDIM * NEXP; i += 256) srw[i] = rw[i];
    __syncthreads();
    const int warp = tid >> 5, lane = tid & 31;
    const int t = blockIdx.x * 8 + warp;
    const float* xr = x + (size_t)t * HDIM;
    float acc[NEXP];
#pragma unroll
    for (int e = 0; e < NEXP; e++) acc[e] = 0.f;
#pragma unroll
    for (int j = 0; j < 16; j++) {
        int h = lane + j * 32;
        float xv = xr[h];
        const float* r = &srw[h * NEXP];
#pragma unroll
        for (int e = 0; e < NEXP; e++) acc[e] += xv * r[e];
    }
#pragma unroll
    for (int off = 16; off; off >>= 1)
#pragma unroll
        for (int e = 0; e < NEXP; e++)
            acc[e] += __shfl_down_sync(0xffffffffu, acc[e], off);
    if (lane == 0) {
        int i0 = 0;
#pragma unroll
        for (int e = 1; e < NEXP; e++) if (acc[e] > acc[i0]) i0 = e;
        int i1 = (i0 == 0) ? 1 : 0;
#pragma unroll
        for (int e = 0; e < NEXP; e++)
            if (e != i0 && acc[e] > acc[i1]) i1 = e;
        float ex = expf(acc[i1] - acc[i0]);
        float inv = 1.0f / (1.0f + ex);
        g_eidx[2 * t] = i0;  g_eidx[2 * t + 1] = i1;
        g_wgt[2 * t] = inv;  g_wgt[2 * t + 1] = ex * inv;
    }
}

// ---------------- 2) stable counting sort ------------------------------------
__global__ void assign_kernel() {
    __shared__ int sh[NEXP][1024];
    const int tid = threadIdx.x;
    for (int i = tid; i < NEXP * CAP; i += 1024) g_s2t[i] = -1;
    const int base = tid * 32;
    int lc[NEXP];
#pragma unroll
    for (int e = 0; e < NEXP; e++) lc[e] = 0;
    for (int j = 0; j < 32; j++) lc[g_eidx[base + j]]++;
#pragma unroll
    for (int e = 0; e < NEXP; e++) sh[e][tid] = lc[e];
    __syncthreads();
    for (int off = 1; off < 1024; off <<= 1) {
        int v[NEXP];
        bool p = (tid >= off);
        if (p) {
#pragma unroll
            for (int e = 0; e < NEXP; e++) v[e] = sh[e][tid - off];
        }
        __syncthreads();
        if (p) {
#pragma unroll
            for (int e = 0; e < NEXP; e++) sh[e][tid] += v[e];
        }
        __syncthreads();
    }
    if (tid == 0) {
#pragma unroll
        for (int e = 0; e < NEXP; e++) g_cnt[e] = min(sh[e][1023], CAP);
    }
    int run[NEXP];
#pragma unroll
    for (int e = 0; e < NEXP; e++) run[e] = sh[e][tid] - lc[e];
    for (int j = 0; j < 32; j++) {
        int i = base + j;
        int e = g_eidx[i];
        int s = run[e]++;
        g_slot[i] = s;
        if (s < CAP) g_s2t[e * CAP + s] = (i >> 1);
    }
}

// ---------------- 3) fp32 -> fp16 hi/lo split --------------------------------
__global__ void split_x_kernel(const float* __restrict__ x) {
    size_t i = ((size_t)blockIdx.x * 256 + threadIdx.x) * 4;
    float4 v = *(const float4*)(x + i);
    __half h0 = __float2half(v.x), h1 = __float2half(v.y);
    __half h2 = __float2half(v.z), h3 = __float2half(v.w);
    __half l0 = __float2half(v.x - __half2float(h0));
    __half l1 = __float2half(v.y - __half2float(h1));
    __half l2 = __float2half(v.z - __half2float(h2));
    __half l3 = __float2half(v.w - __half2float(h3));
    __half2 ha = __halves2half2(h0, h1), hb = __halves2half2(h2, h3);
    __half2 la = __halves2half2(l0, l1), lb = __halves2half2(l2, l3);
    *(uint2*)(g_xhi + i) = make_uint2(*(unsigned*)&ha, *(unsigned*)&hb);
    *(uint2*)(g_xlo + i) = make_uint2(*(unsigned*)&la, *(unsigned*)&lb);
}

// W [E][R][C] f32 -> transpose to fp16 hi into device globals (no lo needed).
template <int WHICH>   // 1 -> g_w1t_hi (R=HDIM,C=FDIM), 2 -> g_w2t_hi (R=FDIM,C=HDIM)
__global__ void tsplit_kernel(const float* __restrict__ W) {
    constexpr int R = (WHICH == 1) ? HDIM : FDIM;
    constexpr int C = (WHICH == 1) ? FDIM : HDIM;
    __half* Oh = (WHICH == 1) ? g_w1t_hi : g_w2t_hi;

    __shared__ float t[32][33];
    const int e = blockIdx.z;
    const float* w = W + (size_t)e * R * C;
    __half* oh = Oh + (size_t)e * R * C;
    const int c0 = blockIdx.x * 32, r0 = blockIdx.y * 32;
    const int tx = threadIdx.x, ty = threadIdx.y;
#pragma unroll
    for (int j = 0; j < 4; j++)
        t[ty * 4 + j][tx] = w[(size_t)(r0 + ty * 4 + j) * C + c0 + tx];
    __syncthreads();
#pragma unroll
    for (int j = 0; j < 4; j++) {
        float v = t[tx][ty * 4 + j];
        size_t o = (size_t)(c0 + ty * 4 + j) * R + r0 + tx;
        oh[o] = __float2half(v);
    }
}

// ---------------- 4) grouped GEMM via mma.sync (split-fp16, 2 passes) ---------
// Block tile 128x128, 8 warps (warp tile 32x64), K-chunk 32, 2-stage cp.async
// in dynamic smem (48KB/CTA, 2 CTAs/SM).
// Row pitch 64B; swizzle: kb ^= ((row>>1)&3)<<4 => 8 ldmatrix rows phase-distinct.
#define ROWB 64
#define MATB (128 * ROWB)       // 8192
#define STGB (3 * MATB)         // 24576: Ahi, Alo, Bhi
#define SMEM_DYN (2 * STGB)     // 49152

template <bool FIRST>
__global__ __launch_bounds__(256, 2) void moe_mma(const float* __restrict__ Bias) {
    constexpr int KD = FIRST ? HDIM : FDIM;
    constexpr int ND = FIRST ? FDIM : HDIM;
    constexpr int NC = KD / 32;

    const __half* Ahi_g = FIRST ? g_xhi : g_hhi;
    const __half* Alo_g = FIRST ? g_xlo : g_hlo;
    const __half* Bhi_g = FIRST ? g_w1t_hi : g_w2t_hi;

    const int e = blockIdx.z;
    const int m0 = blockIdx.y * 128;
    const int n0 = blockIdx.x * 128;
    if (m0 >= g_cnt[e]) return;

    __shared__ float sbias[128];
    extern __shared__ __align__(16) char buf[];
    const uint32_t sbuf = smem_u32(buf);

    const int tid = threadIdx.x, wid = tid >> 5, lane = tid & 31;
    const int warp_m = wid & 3, warp_n = wid >> 2;

    if (tid < 128) sbias[tid] = Bias[e * ND + n0 + tid];

    // ---- loader coords: row = tid>>1; two 16B chunks kb0, kb0+32 -------------
    const int lrow = tid >> 1;
    const int kb0 = (tid & 1) * 16;
    const uint32_t lsw = (((uint32_t)lrow >> 1) & 3u) << 4;
    const uint32_t dst0 = (uint32_t)lrow * ROWB + ((uint32_t)kb0 ^ lsw);
    const uint32_t dst1 = (uint32_t)lrow * ROWB + ((uint32_t)(kb0 + 32) ^ lsw);

    const char* srcA_h;
    const char* srcA_l;
    bool av = true;
    if (FIRST) {
        int t = g_s2t[e * CAP + m0 + lrow];
        av = (t >= 0);
        srcA_h = (const char*)(Ahi_g + (size_t)(av ? t : 0) * KD) + kb0;
        srcA_l = (const char*)(Alo_g + (size_t)(av ? t : 0) * KD) + kb0;
    } else {
        size_t ro = ((size_t)e * CAP + m0 + lrow) * (size_t)KD;
        srcA_h = (const char*)(Ahi_g + ro) + kb0;
        srcA_l = (const char*)(Alo_g + ro) + kb0;
    }
    size_t bo = ((size_t)e * ND + n0 + lrow) * (size_t)KD;
    const char* srcB_h = (const char*)(Bhi_g + bo) + kb0;
    const char* zsrc = (const char*)g_zero + kb0;

    auto load_chunk = [&](int c, int s) {
        const uint32_t base = sbuf + (uint32_t)s * STGB;
        const int kB = c * 64;
        cp16(base + dst0,            av ? srcA_h + kB : zsrc);
        cp16(base + dst1,            av ? srcA_h + kB + 32 : zsrc);
        cp16(base + dst0 + MATB,     av ? srcA_l + kB : zsrc);
        cp16(base + dst1 + MATB,     av ? srcA_l + kB + 32 : zsrc);
        cp16(base + dst0 + 2 * MATB, srcB_h + kB);
        cp16(base + dst1 + 2 * MATB, srcB_h + kB + 32);
        CP_COMMIT();
    };

    float acc[2][8][4];
#pragma unroll
    for (int mi = 0; mi < 2; mi++)
#pragma unroll
        for (int nj = 0; nj < 8; nj++)
#pragma unroll
            for (int q = 0; q < 4; q++) acc[mi][nj][q] = 0.f;

    // ---- ldmatrix lane addressing (same swizzle as writer) -------------------
    const int fr_row = lane & 15;
    const uint32_t fr_kb = (uint32_t)((lane >> 4) * 16);
    const uint32_t rsw = (((uint32_t)fr_row >> 1) & 3u) << 4;
    const uint32_t aoff = ((uint32_t)(warp_m * 32 + fr_row)) * ROWB;
    const uint32_t boff = ((uint32_t)(warp_n * 64 + fr_row)) * ROWB + 2 * MATB;

    load_chunk(0, 0);
    for (int cc = 0; cc < NC; ++cc) {
        const int s = cc & 1;
        if (cc + 1 < NC) { load_chunk(cc + 1, s ^ 1); CP_WAIT(1); }
        else             { CP_WAIT(0); }
        __syncthreads();

        const uint32_t base = sbuf + (uint32_t)s * STGB;

#pragma unroll
        for (int kk = 0; kk < 2; kk++) {
            const uint32_t kbsw = ((uint32_t)(kk * 32) + fr_kb) ^ rsw;
            uint32_t af[2][4], al[2][4], bf[8][2];
#pragma unroll
            for (int mi = 0; mi < 2; mi++) {
                uint32_t a0 = base + aoff + (uint32_t)mi * 16 * ROWB + kbsw;
                ldsm4(af[mi], a0);
                ldsm4(al[mi], a0 + MATB);
            }
#pragma unroll
            for (int j = 0; j < 4; j++) {
                uint32_t t4[4];
                ldsm4(t4, base + boff + (uint32_t)j * 16 * ROWB + kbsw);
                bf[2 * j][0] = t4[0];     bf[2 * j][1] = t4[2];
                bf[2 * j + 1][0] = t4[1]; bf[2 * j + 1][1] = t4[3];
            }
#pragma unroll
            for (int mi = 0; mi < 2; mi++)
#pragma unroll
                for (int nj = 0; nj < 8; nj++) {
                    mma16816(acc[mi][nj], af[mi], bf[nj]);
                    mma16816(acc[mi][nj], al[mi], bf[nj]);
                }
        }
        __syncthreads();
    }

    // ---- epilogue ----
    const int rbase = m0 + warp_m * 32 + (lane >> 2);
    const int cbase = warp_n * 64 + (lane & 3) * 2;
#pragma unroll
    for (int mi = 0; mi < 2; mi++) {
#pragma unroll
        for (int nj = 0; nj < 8; nj++) {
            int col = cbase + nj * 8;
            float bia0 = sbias[col], bia1 = sbias[col + 1];
#pragma unroll
            for (int hh = 0; hh < 2; hh++) {
                int r = rbase + mi * 16 + hh * 8;
                float z0 = acc[mi][nj][2 * hh] + bia0;
                float z1 = acc[mi][nj][2 * hh + 1] + bia1;
                if (FIRST) {
                    float u0 = 0.7978845608028654f * (z0 + 0.044715f * z0 * z0 * z0);
                    float u1 = 0.7978845608028654f * (z1 + 0.044715f * z1 * z1 * z1);
                    float g0 = 0.5f * z0 * (1.0f + tanhf(u0));
                    float g1 = 0.5f * z1 * (1.0f + tanhf(u1));
                    __half h0 = __float2half(g0);
                    __half h1 = __float2half(g1);
                    __half l0 = __float2half(g0 - __half2float(h0));
                    __half l1 = __float2half(g1 - __half2float(h1));
                    __half2 hp = __halves2half2(h0, h1);
                    __half2 lp = __halves2half2(l0, l1);
                    size_t off = ((size_t)e * CAP + r) * FDIM + n0 + col;
                    *(unsigned*)(g_hhi + off) = *(unsigned*)&hp;
                    *(unsigned*)(g_hlo + off) = *(unsigned*)&lp;
                } else {
                    size_t off = ((size_t)e * CAP + r) * HDIM + n0 + col;
                    *(float2*)(g_eo + off) = make_float2(z0, z1);
                }
            }
        }
    }
}

// ---------------- 5) combine ---------------------------------------------------
__global__ void combine_kernel(float* __restrict__ out) {
    const int tid = threadIdx.x;
    const int warp = tid >> 5, lane = tid & 31;
    const int t = blockIdx.x * 8 + warp;
    float4 acc[4];
#pragma unroll
    for (int q = 0; q < 4; q++) acc[q] = make_float4(0.f, 0.f, 0.f, 0.f);
#pragma unroll
    for (int k = 0; k < 2; k++) {
        int s = g_slot[2 * t + k];
        if (s < CAP) {
            int e = g_eidx[2 * t + k];
            float w = g_wgt[2 * t + k];
            const float4* src = (const float4*)(g_eo + ((size_t)e * CAP + s) * HDIM);
#pragma unroll
            for (int q = 0; q < 4; q++) {
                float4 v = src[lane + q * 32];
                acc[q].x += w * v.x; acc[q].y += w * v.y;
                acc[q].z += w * v.z; acc[q].w += w * v.w;
            }
        }
    }
    float4* o = (float4*)(out + (size_t)t * HDIM);
#pragma unroll
    for (int q = 0; q < 4; q++) o[lane + q * 32] = acc[q];
}

// ---------------- launch -------------------------------------------------------
extern "C" void kernel_launch(void* const* d_in, const int* in_sizes, int n_in,
                              void* d_out, int out_size) {
    const float* x  = (const float*)d_in[0];
    const float* rw = (const float*)d_in[1];
    const float* w1 = (const float*)d_in[2];
    const float* b1 = (const float*)d_in[3];
    const float* w2 = (const float*)d_in[4];
    const float* b2 = (const float*)d_in[5];
    float* out = (float*)d_out;

    cudaFuncSetAttribute(moe_mma<true>,
                         cudaFuncAttributeMaxDynamicSharedMemorySize, SMEM_DYN);
    cudaFuncSetAttribute(moe_mma<false>,
                         cudaFuncAttributeMaxDynamicSharedMemorySize, SMEM_DYN);

    router_kernel<<<NTOK / 8, 256>>>(x, rw);
    assign_kernel<<<1, 1024>>>();
    split_x_kernel<<<(NTOK * HDIM) / 1024, 256>>>(x);
    tsplit_kernel<1><<<dim3(FDIM / 32, HDIM / 32, NEXP), dim3(32, 8)>>>(w1);
    tsplit_kernel<2><<<dim3(HDIM / 32, FDIM / 32, NEXP), dim3(32, 8)>>>(w2);
    moe_mma<true><<<dim3(FDIM / 128, CAP / 128, NEXP), 256, SMEM_DYN>>>(b1);
    moe_mma<false><<<dim3(HDIM / 128, CAP / 128, NEXP), 256, SMEM_DYN>>>(b2);
    combine_kernel<<<NTOK / 8, 256>>>(out);
}

// round 12
// speedup vs baseline: 1.2754x; 1.2754x over previous
#include <cuda_runtime.h>
#include <cuda_fp16.h>
#include <math.h>
#include <stdint.h>

// Problem constants (B=4, T=4096, H=512, E=8, K=2, F=2048, cap=5120)
#define NTOK 16384
#define HDIM 512
#define NEXP 8
#define FDIM 2048
#define CAP  5120
#define NK   32768

// ---------------- persistent device scratch (device-side refs ONLY) -----------
__device__ int   g_eidx[NK];
__device__ float g_wgt[NK];
__device__ int   g_slot[NK];
__device__ int   g_s2t[NEXP * CAP];
__device__ int   g_cnt[NEXP];
__device__ __align__(256) __half g_zero[128];

__device__ __align__(256) __half g_xhi[(size_t)NTOK * HDIM];
__device__ __align__(256) __half g_xlo[(size_t)NTOK * HDIM];
__device__ __align__(256) __half g_w1t_hi[(size_t)NEXP * FDIM * HDIM]; // [e][f][h]
__device__ __align__(256) __half g_w2t_hi[(size_t)NEXP * HDIM * FDIM]; // [e][h][f]
__device__ __align__(256) __half g_hhi[(size_t)NEXP * CAP * FDIM];
__device__ __align__(256) float g_eo[(size_t)NEXP * CAP * HDIM];

// ---------------- PTX helpers (portable sm_80+) -------------------------------
__device__ __forceinline__ uint32_t smem_u32(const void* p) {
    uint32_t a;
    asm("{ .reg .u64 t; cvta.to.shared.u64 t, %1; cvt.u32.u64 %0, t; }"
        : "=r"(a) : "l"(p));
    return a;
}
__device__ __forceinline__ void cp16(uint32_t dst, const void* src) {
    asm volatile("cp.async.cg.shared.global [%0], [%1], 16;"
                 :: "r"(dst), "l"(src) : "memory");
}
#define CP_COMMIT() asm volatile("cp.async.commit_group;" ::: "memory")
#define CP_WAIT(n)  asm volatile("cp.async.wait_group %0;" :: "n"(n) : "memory")

__device__ __forceinline__ void ldsm4(uint32_t r[4], uint32_t addr) {
    asm volatile("ldmatrix.sync.aligned.m8n8.x4.shared.b16 {%0,%1,%2,%3}, [%4];"
                 : "=r"(r[0]), "=r"(r[1]), "=r"(r[2]), "=r"(r[3]) : "r"(addr));
}
__device__ __forceinline__ void mma16816(float c[4], const uint32_t a[4],
                                         const uint32_t b[2]) {
    asm volatile(
        "mma.sync.aligned.m16n8k16.row.col.f32.f16.f16.f32 "
        "{%0,%1,%2,%3},{%4,%5,%6,%7},{%8,%9},{%0,%1,%2,%3};"
        : "+f"(c[0]), "+f"(c[1]), "+f"(c[2]), "+f"(c[3])
        : "r"(a[0]), "r"(a[1]), "r"(a[2]), "r"(a[3]), "r"(b[0]), "r"(b[1]));
}

// ---------------- 1) router ---------------------------------------------------
__global__ void router_kernel(const float* __restrict__ x,
                              const float* __restrict__ rw) {
    __shared__ float srw[HDIM * NEXP];
    const int tid = threadIdx.x;
    for (int i = tid; i < HDIM * NEXP; i += 256) srw[i] = rw[i];
    __syncthreads();
    const int warp = tid >> 5, lane = tid & 31;
    const int t = blockIdx.x * 8 + warp;
    const float* xr = x + (size_t)t * HDIM;
    float acc[NEXP];
#pragma unroll
    for (int e = 0; e < NEXP; e++) acc[e] = 0.f;
#pragma unroll
    for (int j = 0; j < 16; j++) {
        int h = lane + j * 32;
        float xv = xr[h];
        const float* r = &srw[h * NEXP];
#pragma unroll
        for (int e = 0; e < NEXP; e++) acc[e] += xv * r[e];
    }
#pragma unroll
    for (int off = 16; off; off >>= 1)
#pragma unroll
        for (int e = 0; e < NEXP; e++)
            acc[e] += __shfl_down_sync(0xffffffffu, acc[e], off);
    if (lane == 0) {
        int i0 = 0;
#pragma unroll
        for (int e = 1; e < NEXP; e++) if (acc[e] > acc[i0]) i0 = e;
        int i1 = (i0 == 0) ? 1 : 0;
#pragma unroll
        for (int e = 0; e < NEXP; e++)
            if (e != i0 && acc[e] > acc[i1]) i1 = e;
        float ex = expf(acc[i1] - acc[i0]);
        float inv = 1.0f / (1.0f + ex);
        g_eidx[2 * t] = i0;  g_eidx[2 * t + 1] = i1;
        g_wgt[2 * t] = inv;  g_wgt[2 * t + 1] = ex * inv;
    }
}

// ---------------- 2) stable counting sort ------------------------------------
__global__ void assign_kernel() {
    __shared__ int sh[NEXP][1024];
    const int tid = threadIdx.x;
    for (int i = tid; i < NEXP * CAP; i += 1024) g_s2t[i] = -1;
    const int base = tid * 32;
    int lc[NEXP];
#pragma unroll
    for (int e = 0; e < NEXP; e++) lc[e] = 0;
    for (int j = 0; j < 32; j++) lc[g_eidx[base + j]]++;
#pragma unroll
    for (int e = 0; e < NEXP; e++) sh[e][tid] = lc[e];
    __syncthreads();
    for (int off = 1; off < 1024; off <<= 1) {
        int v[NEXP];
        bool p = (tid >= off);
        if (p) {
#pragma unroll
            for (int e = 0; e < NEXP; e++) v[e] = sh[e][tid - off];
        }
        __syncthreads();
        if (p) {
#pragma unroll
            for (int e = 0; e < NEXP; e++) sh[e][tid] += v[e];
        }
        __syncthreads();
    }
    if (tid == 0) {
#pragma unroll
        for (int e = 0; e < NEXP; e++) g_cnt[e] = min(sh[e][1023], CAP);
    }
    int run[NEXP];
#pragma unroll
    for (int e = 0; e < NEXP; e++) run[e] = sh[e][tid] - lc[e];
    for (int j = 0; j < 32; j++) {
        int i = base + j;
        int e = g_eidx[i];
        int s = run[e]++;
        g_slot[i] = s;
        if (s < CAP) g_s2t[e * CAP + s] = (i >> 1);
    }
}

// ---------------- 3) fp32 -> fp16 hi/lo split --------------------------------
__global__ void split_x_kernel(const float* __restrict__ x) {
    size_t i = ((size_t)blockIdx.x * 256 + threadIdx.x) * 4;
    float4 v = *(const float4*)(x + i);
    __half h0 = __float2half(v.x), h1 = __float2half(v.y);
    __half h2 = __float2half(v.z), h3 = __float2half(v.w);
    __half l0 = __float2half(v.x - __half2float(h0));
    __half l1 = __float2half(v.y - __half2float(h1));
    __half l2 = __float2half(v.z - __half2float(h2));
    __half l3 = __float2half(v.w - __half2float(h3));
    __half2 ha = __halves2half2(h0, h1), hb = __halves2half2(h2, h3);
    __half2 la = __halves2half2(l0, l1), lb = __halves2half2(l2, l3);
    *(uint2*)(g_xhi + i) = make_uint2(*(unsigned*)&ha, *(unsigned*)&hb);
    *(uint2*)(g_xlo + i) = make_uint2(*(unsigned*)&la, *(unsigned*)&lb);
}

// W [E][R][C] f32 -> transpose to fp16 hi into device globals (no lo needed).
template <int WHICH>   // 1 -> g_w1t_hi (R=HDIM,C=FDIM), 2 -> g_w2t_hi (R=FDIM,C=HDIM)
__global__ void tsplit_kernel(const float* __restrict__ W) {
    constexpr int R = (WHICH == 1) ? HDIM : FDIM;
    constexpr int C = (WHICH == 1) ? FDIM : HDIM;
    __half* Oh = (WHICH == 1) ? g_w1t_hi : g_w2t_hi;

    __shared__ float t[32][33];
    const int e = blockIdx.z;
    const float* w = W + (size_t)e * R * C;
    __half* oh = Oh + (size_t)e * R * C;
    const int c0 = blockIdx.x * 32, r0 = blockIdx.y * 32;
    const int tx = threadIdx.x, ty = threadIdx.y;
#pragma unroll
    for (int j = 0; j < 4; j++)
        t[ty * 4 + j][tx] = w[(size_t)(r0 + ty * 4 + j) * C + c0 + tx];
    __syncthreads();
#pragma unroll
    for (int j = 0; j < 4; j++) {
        float v = t[tx][ty * 4 + j];
        size_t o = (size_t)(c0 + ty * 4 + j) * R + r0 + tx;
        oh[o] = __float2half(v);
    }
}

// ---------------- 4) grouped GEMM via mma.sync (fp16) -------------------------
// Block tile 128x128, 8 warps (warp tile 32x64), K-chunk 16, 2-stage cp.async.
// GEMM1 (FIRST): (Ahi+Alo) x Bhi — 2 passes, A exact to ~21 bits.
// GEMM2        :  Ahi x Bhi      — 1 pass (h's fp16 rounding ~2.8e-4 RMS).
#define ROWB 32
#define MATB (128 * ROWB)       // 4096
#define STGB (3 * MATB)         // 12288: Ahi, Alo, Bhi (GEMM2 leaves Alo unused)

template <bool FIRST>
__global__ __launch_bounds__(256, 2) void moe_mma(const float* __restrict__ Bias) {
    constexpr int KD = FIRST ? HDIM : FDIM;
    constexpr int ND = FIRST ? FDIM : HDIM;
    constexpr int NC = KD / 16;

    const __half* Ahi_g = FIRST ? g_xhi : g_hhi;
    const __half* Alo_g = g_xlo;                    // only read when FIRST
    const __half* Bhi_g = FIRST ? g_w1t_hi : g_w2t_hi;

    const int e = blockIdx.z;
    const int m0 = blockIdx.y * 128;
    const int n0 = blockIdx.x * 128;
    if (m0 >= g_cnt[e]) return;

    __shared__ float sbias[128];
    __shared__ __align__(16) char buf[2 * STGB];
    const uint32_t sbuf = smem_u32(buf);

    const int tid = threadIdx.x, wid = tid >> 5, lane = tid & 31;
    const int warp_m = wid & 3, warp_n = wid >> 2;

    if (tid < 128) sbias[tid] = Bias[e * ND + n0 + tid];

    // ---- loader coords: each thread owns (row = tid>>1, 16B half = tid&1) ----
    const int lrow = tid >> 1;
    const int half = (tid & 1) * 16;
    const uint32_t dsto = (uint32_t)lrow * ROWB +
                          ((uint32_t)half ^ (((lrow >> 2) & 1u) << 4));

    const char* srcA_h;
    const char* srcA_l = nullptr;
    bool av = true;
    if (FIRST) {
        int t = g_s2t[e * CAP + m0 + lrow];
        av = (t >= 0);
        srcA_h = (const char*)(Ahi_g + (size_t)(av ? t : 0) * KD) + half;
        srcA_l = (const char*)(Alo_g + (size_t)(av ? t : 0) * KD) + half;
    } else {
        size_t ro = ((size_t)e * CAP + m0 + lrow) * (size_t)KD;
        srcA_h = (const char*)(Ahi_g + ro) + half;
    }
    size_t bo = ((size_t)e * ND + n0 + lrow) * (size_t)KD;
    const char* srcB_h = (const char*)(Bhi_g + bo) + half;
    const char* zsrc = (const char*)g_zero + half;

    auto load_chunk = [&](int c, int s) {
        const uint32_t base = sbuf + (uint32_t)s * STGB;
        const int kB = c * 32;
        cp16(base + dsto, av ? srcA_h + kB : zsrc);
        if (FIRST) cp16(base + dsto + MATB, av ? srcA_l + kB : zsrc);
        cp16(base + dsto + 2 * MATB, srcB_h + kB);
        CP_COMMIT();
    };

    float acc[2][8][4];
#pragma unroll
    for (int mi = 0; mi < 2; mi++)
#pragma unroll
        for (int nj = 0; nj < 8; nj++)
#pragma unroll
            for (int q = 0; q < 4; q++) acc[mi][nj][q] = 0.f;

    // ---- ldmatrix lane addressing (matches writer's swizzle) ----
    const int fr_row = lane & 15;
    const uint32_t fr_kb = (uint32_t)((lane >> 4) * 16);
    const uint32_t kbsw = fr_kb ^ (((uint32_t)fr_row & 4u) << 2);
    const uint32_t aoff = ((uint32_t)(warp_m * 32 + fr_row)) * ROWB + kbsw;
    const uint32_t boff = ((uint32_t)(warp_n * 64 + fr_row)) * ROWB + kbsw + 2 * MATB;

    load_chunk(0, 0);
    for (int cc = 0; cc < NC; ++cc) {
        const int s = cc & 1;
        if (cc + 1 < NC) { load_chunk(cc + 1, s ^ 1); CP_WAIT(1); }
        else             { CP_WAIT(0); }
        __syncthreads();

        const uint32_t base = sbuf + (uint32_t)s * STGB;

        uint32_t af[2][4], al[2][4], bf[8][2];
#pragma unroll
        for (int mi = 0; mi < 2; mi++) {
            uint32_t a0 = base + aoff + (uint32_t)mi * 16 * ROWB;
            ldsm4(af[mi], a0);
            if (FIRST) ldsm4(al[mi], a0 + MATB);
        }
#pragma unroll
        for (int j = 0; j < 4; j++) {
            uint32_t t4[4];
            ldsm4(t4, base + boff + (uint32_t)j * 16 * ROWB);
            bf[2 * j][0] = t4[0];     bf[2 * j][1] = t4[2];
            bf[2 * j + 1][0] = t4[1]; bf[2 * j + 1][1] = t4[3];
        }
#pragma unroll
        for (int mi = 0; mi < 2; mi++)
#pragma unroll
            for (int nj = 0; nj < 8; nj++) {
                mma16816(acc[mi][nj], af[mi], bf[nj]);
                if (FIRST) mma16816(acc[mi][nj], al[mi], bf[nj]);
            }
        __syncthreads();
    }

    // ---- epilogue ----
    const int rbase = m0 + warp_m * 32 + (lane >> 2);
    const int cbase = warp_n * 64 + (lane & 3) * 2;
#pragma unroll
    for (int mi = 0; mi < 2; mi++) {
#pragma unroll
        for (int nj = 0; nj < 8; nj++) {
            int col = cbase + nj * 8;
            float bia0 = sbias[col], bia1 = sbias[col + 1];
#pragma unroll
            for (int hh = 0; hh < 2; hh++) {
                int r = rbase + mi * 16 + hh * 8;
                float z0 = acc[mi][nj][2 * hh] + bia0;
                float z1 = acc[mi][nj][2 * hh + 1] + bia1;
                if (FIRST) {
                    float u0 = 0.7978845608028654f * (z0 + 0.044715f * z0 * z0 * z0);
                    float u1 = 0.7978845608028654f * (z1 + 0.044715f * z1 * z1 * z1);
                    float g0 = 0.5f * z0 * (1.0f + tanhf(u0));
                    float g1 = 0.5f * z1 * (1.0f + tanhf(u1));
                    __half2 hp = __halves2half2(__float2half(g0), __float2half(g1));
                    size_t off = ((size_t)e * CAP + r) * FDIM + n0 + col;
                    *(unsigned*)(g_hhi + off) = *(unsigned*)&hp;
                } else {
                    size_t off = ((size_t)e * CAP + r) * HDIM + n0 + col;
                    *(float2*)(g_eo + off) = make_float2(z0, z1);
                }
            }
        }
    }
}

// ---------------- 5) combine ---------------------------------------------------
__global__ void combine_kernel(float* __restrict__ out) {
    const int tid = threadIdx.x;
    const int warp = tid >> 5, lane = tid & 31;
    const int t = blockIdx.x * 8 + warp;
    float4 acc[4];
#pragma unroll
    for (int q = 0; q < 4; q++) acc[q] = make_float4(0.f, 0.f, 0.f, 0.f);
#pragma unroll
    for (int k = 0; k < 2; k++) {
        int s = g_slot[2 * t + k];
        if (s < CAP) {
            int e = g_eidx[2 * t + k];
            float w = g_wgt[2 * t + k];
            const float4* src = (const float4*)(g_eo + ((size_t)e * CAP + s) * HDIM);
#pragma unroll
            for (int q = 0; q < 4; q++) {
                float4 v = src[lane + q * 32];
                acc[q].x += w * v.x; acc[q].y += w * v.y;
                acc[q].z += w * v.z; acc[q].w += w * v.w;
            }
        }
    }
    float4* o = (float4*)(out + (size_t)t * HDIM);
#pragma unroll
    for (int q = 0; q < 4; q++) o[lane + q * 32] = acc[q];
}

// ---------------- launch -------------------------------------------------------
extern "C" void kernel_launch(void* const* d_in, const int* in_sizes, int n_in,
                              void* d_out, int out_size) {
    const float* x  = (const float*)d_in[0];
    const float* rw = (const float*)d_in[1];
    const float* w1 = (const float*)d_in[2];
    const float* b1 = (const float*)d_in[3];
    const float* w2 = (const float*)d_in[4];
    const float* b2 = (const float*)d_in[5];
    float* out = (float*)d_out;

    router_kernel<<<NTOK / 8, 256>>>(x, rw);
    assign_kernel<<<1, 1024>>>();
    split_x_kernel<<<(NTOK * HDIM) / 1024, 256>>>(x);
    tsplit_kernel<1><<<dim3(FDIM / 32, HDIM / 32, NEXP), dim3(32, 8)>>>(w1);
    tsplit_kernel<2><<<dim3(HDIM / 32, FDIM / 32, NEXP), dim3(32, 8)>>>(w2);
    moe_mma<true><<<dim3(FDIM / 128, CAP / 128, NEXP), 256>>>(b1);
    moe_mma<false><<<dim3(HDIM / 128, CAP / 128, NEXP), 256>>>(b2);
    combine_kernel<<<NTOK / 8, 256>>>(out);
}

// round 13
// speedup vs baseline: 1.5562x; 1.2202x over previous
#include <cuda_runtime.h>
#include <cuda_fp16.h>
#include <math.h>
#include <stdint.h>

// Problem constants (B=4, T=4096, H=512, E=8, K=2, F=2048, cap=5120)
#define NTOK 16384
#define HDIM 512
#define NEXP 8
#define FDIM 2048
#define CAP  5120
#define NK   32768

// ---------------- persistent device scratch (device-side refs ONLY) -----------
__device__ int   g_eidx[NK];
__device__ float g_wgt[NK];
__device__ int   g_slot[NK];
__device__ int   g_s2t[NEXP * CAP];
__device__ int   g_cnt[NEXP];
__device__ __align__(256) __half g_zero[128];

__device__ __align__(256) __half g_xhi[(size_t)NTOK * HDIM];
__device__ __align__(256) __half g_w1t_hi[(size_t)NEXP * FDIM * HDIM]; // [e][f][h]
__device__ __align__(256) __half g_w2t_hi[(size_t)NEXP * HDIM * FDIM]; // [e][h][f]
__device__ __align__(256) __half g_hhi[(size_t)NEXP * CAP * FDIM];
__device__ __align__(256) float g_eo[(size_t)NEXP * CAP * HDIM];

// ---------------- PTX helpers (portable sm_80+) -------------------------------
__device__ __forceinline__ uint32_t smem_u32(const void* p) {
    uint32_t a;
    asm("{ .reg .u64 t; cvta.to.shared.u64 t, %1; cvt.u32.u64 %0, t; }"
        : "=r"(a) : "l"(p));
    return a;
}
__device__ __forceinline__ void cp16(uint32_t dst, const void* src) {
    asm volatile("cp.async.cg.shared.global [%0], [%1], 16;"
                 :: "r"(dst), "l"(src) : "memory");
}
#define CP_COMMIT() asm volatile("cp.async.commit_group;" ::: "memory")
#define CP_WAIT(n)  asm volatile("cp.async.wait_group %0;" :: "n"(n) : "memory")

__device__ __forceinline__ void ldsm4(uint32_t r[4], uint32_t addr) {
    asm volatile("ldmatrix.sync.aligned.m8n8.x4.shared.b16 {%0,%1,%2,%3}, [%4];"
                 : "=r"(r[0]), "=r"(r[1]), "=r"(r[2]), "=r"(r[3]) : "r"(addr));
}
__device__ __forceinline__ void mma16816(float c[4], const uint32_t a[4],
                                         const uint32_t b[2]) {
    asm volatile(
        "mma.sync.aligned.m16n8k16.row.col.f32.f16.f16.f32 "
        "{%0,%1,%2,%3},{%4,%5,%6,%7},{%8,%9},{%0,%1,%2,%3};"
        : "+f"(c[0]), "+f"(c[1]), "+f"(c[2]), "+f"(c[3])
        : "r"(a[0]), "r"(a[1]), "r"(a[2]), "r"(a[3]), "r"(b[0]), "r"(b[1]));
}

// ---------------- 1) router ---------------------------------------------------
__global__ void router_kernel(const float* __restrict__ x,
                              const float* __restrict__ rw) {
    __shared__ float srw[HDIM * NEXP];
    const int tid = threadIdx.x;
    for (int i = tid; i < HDIM * NEXP; i += 256) srw[i] = rw[i];
    __syncthreads();
    const int warp = tid >> 5, lane = tid & 31;
    const int t = blockIdx.x * 8 + warp;
    const float* xr = x + (size_t)t * HDIM;
    float acc[NEXP];
#pragma unroll
    for (int e = 0; e < NEXP; e++) acc[e] = 0.f;
#pragma unroll
    for (int j = 0; j < 16; j++) {
        int h = lane + j * 32;
        float xv = xr[h];
        const float* r = &srw[h * NEXP];
#pragma unroll
        for (int e = 0; e < NEXP; e++) acc[e] += xv * r[e];
    }
#pragma unroll
    for (int off = 16; off; off >>= 1)
#pragma unroll
        for (int e = 0; e < NEXP; e++)
            acc[e] += __shfl_down_sync(0xffffffffu, acc[e], off);
    if (lane == 0) {
        int i0 = 0;
#pragma unroll
        for (int e = 1; e < NEXP; e++) if (acc[e] > acc[i0]) i0 = e;
        int i1 = (i0 == 0) ? 1 : 0;
#pragma unroll
        for (int e = 0; e < NEXP; e++)
            if (e != i0 && acc[e] > acc[i1]) i1 = e;
        float ex = expf(acc[i1] - acc[i0]);
        float inv = 1.0f / (1.0f + ex);
        g_eidx[2 * t] = i0;  g_eidx[2 * t + 1] = i1;
        g_wgt[2 * t] = inv;  g_wgt[2 * t + 1] = ex * inv;
    }
}

// ---------------- 2) stable counting sort ------------------------------------
__global__ void assign_kernel() {
    __shared__ int sh[NEXP][1024];
    const int tid = threadIdx.x;
    for (int i = tid; i < NEXP * CAP; i += 1024) g_s2t[i] = -1;
    const int base = tid * 32;
    int lc[NEXP];
#pragma unroll
    for (int e = 0; e < NEXP; e++) lc[e] = 0;
    for (int j = 0; j < 32; j++) lc[g_eidx[base + j]]++;
#pragma unroll
    for (int e = 0; e < NEXP; e++) sh[e][tid] = lc[e];
    __syncthreads();
    for (int off = 1; off < 1024; off <<= 1) {
        int v[NEXP];
        bool p = (tid >= off);
        if (p) {
#pragma unroll
            for (int e = 0; e < NEXP; e++) v[e] = sh[e][tid - off];
        }
        __syncthreads();
        if (p) {
#pragma unroll
            for (int e = 0; e < NEXP; e++) sh[e][tid] += v[e];
        }
        __syncthreads();
    }
    if (tid == 0) {
#pragma unroll
        for (int e = 0; e < NEXP; e++) g_cnt[e] = min(sh[e][1023], CAP);
    }
    int run[NEXP];
#pragma unroll
    for (int e = 0; e < NEXP; e++) run[e] = sh[e][tid] - lc[e];
    for (int j = 0; j < 32; j++) {
        int i = base + j;
        int e = g_eidx[i];
        int s = run[e]++;
        g_slot[i] = s;
        if (s < CAP) g_s2t[e * CAP + s] = (i >> 1);
    }
}

// ---------------- 3) fp32 -> fp16 convert -------------------------------------
__global__ void split_x_kernel(const float* __restrict__ x) {
    size_t i = ((size_t)blockIdx.x * 256 + threadIdx.x) * 4;
    float4 v = *(const float4*)(x + i);
    __half2 ha = __halves2half2(__float2half(v.x), __float2half(v.y));
    __half2 hb = __halves2half2(__float2half(v.z), __float2half(v.w));
    *(uint2*)(g_xhi + i) = make_uint2(*(unsigned*)&ha, *(unsigned*)&hb);
}

// W [E][R][C] f32 -> transpose to fp16 into device globals.
template <int WHICH>   // 1 -> g_w1t_hi (R=HDIM,C=FDIM), 2 -> g_w2t_hi (R=FDIM,C=HDIM)
__global__ void tsplit_kernel(const float* __restrict__ W) {
    constexpr int R = (WHICH == 1) ? HDIM : FDIM;
    constexpr int C = (WHICH == 1) ? FDIM : HDIM;
    __half* Oh = (WHICH == 1) ? g_w1t_hi : g_w2t_hi;

    __shared__ float t[32][33];
    const int e = blockIdx.z;
    const float* w = W + (size_t)e * R * C;
    __half* oh = Oh + (size_t)e * R * C;
    const int c0 = blockIdx.x * 32, r0 = blockIdx.y * 32;
    const int tx = threadIdx.x, ty = threadIdx.y;
#pragma unroll
    for (int j = 0; j < 4; j++)
        t[ty * 4 + j][tx] = w[(size_t)(r0 + ty * 4 + j) * C + c0 + tx];
    __syncthreads();
#pragma unroll
    for (int j = 0; j < 4; j++) {
        float v = t[tx][ty * 4 + j];
        size_t o = (size_t)(c0 + ty * 4 + j) * R + r0 + tx;
        oh[o] = __float2half(v);
    }
}

// ---------------- 4) grouped GEMM via mma.sync (plain fp16, 1 pass) -----------
// Block tile 128x128, 8 warps (warp tile 32x64), K-chunk 16, 2-stage cp.async.
#define ROWB 32
#define MATB (128 * ROWB)       // 4096
#define STGB (2 * MATB)         // 8192: A, B

template <bool FIRST>
__global__ __launch_bounds__(256, 2) void moe_mma(const float* __restrict__ Bias) {
    constexpr int KD = FIRST ? HDIM : FDIM;
    constexpr int ND = FIRST ? FDIM : HDIM;
    constexpr int NC = KD / 16;

    const __half* A_g = FIRST ? g_xhi : g_hhi;
    const __half* B_g = FIRST ? g_w1t_hi : g_w2t_hi;

    const int e = blockIdx.z;
    const int m0 = blockIdx.y * 128;
    const int n0 = blockIdx.x * 128;
    if (m0 >= g_cnt[e]) return;

    __shared__ float sbias[128];
    __shared__ __align__(16) char buf[2 * STGB];
    const uint32_t sbuf = smem_u32(buf);

    const int tid = threadIdx.x, wid = tid >> 5, lane = tid & 31;
    const int warp_m = wid & 3, warp_n = wid >> 2;

    if (tid < 128) sbias[tid] = Bias[e * ND + n0 + tid];

    // ---- loader coords: each thread owns (row = tid>>1, 16B half = tid&1) ----
    const int lrow = tid >> 1;
    const int half = (tid & 1) * 16;
    const uint32_t dsto = (uint32_t)lrow * ROWB +
                          ((uint32_t)half ^ (((lrow >> 2) & 1u) << 4));

    const char* srcA;
    bool av = true;
    if (FIRST) {
        int t = g_s2t[e * CAP + m0 + lrow];
        av = (t >= 0);
        srcA = (const char*)(A_g + (size_t)(av ? t : 0) * KD) + half;
    } else {
        size_t ro = ((size_t)e * CAP + m0 + lrow) * (size_t)KD;
        srcA = (const char*)(A_g + ro) + half;
    }
    size_t bo = ((size_t)e * ND + n0 + lrow) * (size_t)KD;
    const char* srcB = (const char*)(B_g + bo) + half;
    const char* zsrc = (const char*)g_zero + half;

    auto load_chunk = [&](int c, int s) {
        const uint32_t base = sbuf + (uint32_t)s * STGB;
        const int kB = c * 32;
        cp16(base + dsto,        av ? srcA + kB : zsrc);
        cp16(base + dsto + MATB, srcB + kB);
        CP_COMMIT();
    };

    float acc[2][8][4];
#pragma unroll
    for (int mi = 0; mi < 2; mi++)
#pragma unroll
        for (int nj = 0; nj < 8; nj++)
#pragma unroll
            for (int q = 0; q < 4; q++) acc[mi][nj][q] = 0.f;

    // ---- ldmatrix lane addressing (matches writer's swizzle) ----
    const int fr_row = lane & 15;
    const uint32_t fr_kb = (uint32_t)((lane >> 4) * 16);
    const uint32_t kbsw = fr_kb ^ (((uint32_t)fr_row & 4u) << 2);
    const uint32_t aoff = ((uint32_t)(warp_m * 32 + fr_row)) * ROWB + kbsw;
    const uint32_t boff = ((uint32_t)(warp_n * 64 + fr_row)) * ROWB + kbsw + MATB;

    load_chunk(0, 0);
    for (int cc = 0; cc < NC; ++cc) {
        const int s = cc & 1;
        if (cc + 1 < NC) { load_chunk(cc + 1, s ^ 1); CP_WAIT(1); }
        else             { CP_WAIT(0); }
        __syncthreads();

        const uint32_t base = sbuf + (uint32_t)s * STGB;

        uint32_t af[2][4], bf[8][2];
#pragma unroll
        for (int mi = 0; mi < 2; mi++)
            ldsm4(af[mi], base + aoff + (uint32_t)mi * 16 * ROWB);
#pragma unroll
        for (int j = 0; j < 4; j++) {
            uint32_t t4[4];
            ldsm4(t4, base + boff + (uint32_t)j * 16 * ROWB);
            bf[2 * j][0] = t4[0];     bf[2 * j][1] = t4[2];
            bf[2 * j + 1][0] = t4[1]; bf[2 * j + 1][1] = t4[3];
        }
#pragma unroll
        for (int mi = 0; mi < 2; mi++)
#pragma unroll
            for (int nj = 0; nj < 8; nj++)
                mma16816(acc[mi][nj], af[mi], bf[nj]);
        __syncthreads();
    }

    // ---- epilogue ----
    const int rbase = m0 + warp_m * 32 + (lane >> 2);
    const int cbase = warp_n * 64 + (lane & 3) * 2;
#pragma unroll
    for (int mi = 0; mi < 2; mi++) {
#pragma unroll
        for (int nj = 0; nj < 8; nj++) {
            int col = cbase + nj * 8;
            float bia0 = sbias[col], bia1 = sbias[col + 1];
#pragma unroll
            for (int hh = 0; hh < 2; hh++) {
                int r = rbase + mi * 16 + hh * 8;
                float z0 = acc[mi][nj][2 * hh] + bia0;
                float z1 = acc[mi][nj][2 * hh + 1] + bia1;
                if (FIRST) {
                    float u0 = 0.7978845608028654f * (z0 + 0.044715f * z0 * z0 * z0);
                    float u1 = 0.7978845608028654f * (z1 + 0.044715f * z1 * z1 * z1);
                    float g0 = 0.5f * z0 * (1.0f + tanhf(u0));
                    float g1 = 0.5f * z1 * (1.0f + tanhf(u1));
                    __half2 hp = __halves2half2(__float2half(g0), __float2half(g1));
                    size_t off = ((size_t)e * CAP + r) * FDIM + n0 + col;
                    *(unsigned*)(g_hhi + off) = *(unsigned*)&hp;
                } else {
                    size_t off = ((size_t)e * CAP + r) * HDIM + n0 + col;
                    *(float2*)(g_eo + off) = make_float2(z0, z1);
                }
            }
        }
    }
}

// ---------------- 5) combine ---------------------------------------------------
__global__ void combine_kernel(float* __restrict__ out) {
    const int tid = threadIdx.x;
    const int warp = tid >> 5, lane = tid & 31;
    const int t = blockIdx.x * 8 + warp;
    float4 acc[4];
#pragma unroll
    for (int q = 0; q < 4; q++) acc[q] = make_float4(0.f, 0.f, 0.f, 0.f);
#pragma unroll
    for (int k = 0; k < 2; k++) {
        int s = g_slot[2 * t + k];
        if (s < CAP) {
            int e = g_eidx[2 * t + k];
            float w = g_wgt[2 * t + k];
            const float4* src = (const float4*)(g_eo + ((size_t)e * CAP + s) * HDIM);
#pragma unroll
            for (int q = 0; q < 4; q++) {
                float4 v = src[lane + q * 32];
                acc[q].x += w * v.x; acc[q].y += w * v.y;
                acc[q].z += w * v.z; acc[q].w += w * v.w;
            }
        }
    }
    float4* o = (float4*)(out + (size_t)t * HDIM);
#pragma unroll
    for (int q = 0; q < 4; q++) o[lane + q * 32] = acc[q];
}

// ---------------- launch -------------------------------------------------------
extern "C" void kernel_launch(void* const* d_in, const int* in_sizes, int n_in,
                              void* d_out, int out_size) {
    const float* x  = (const float*)d_in[0];
    const float* rw = (const float*)d_in[1];
    const float* w1 = (const float*)d_in[2];
    const float* b1 = (const float*)d_in[3];
    const float* w2 = (const float*)d_in[4];
    const float* b2 = (const float*)d_in[5];
    float* out = (float*)d_out;

    router_kernel<<<NTOK / 8, 256>>>(x, rw);
    assign_kernel<<<1, 1024>>>();
    split_x_kernel<<<(NTOK * HDIM) / 1024, 256>>>(x);
    tsplit_kernel<1><<<dim3(FDIM / 32, HDIM / 32, NEXP), dim3(32, 8)>>>(w1);
    tsplit_kernel<2><<<dim3(HDIM / 32, FDIM / 32, NEXP), dim3(32, 8)>>>(w2);
    moe_mma<true><<<dim3(FDIM / 128, CAP / 128, NEXP), 256>>>(b1);
    moe_mma<false><<<dim3(HDIM / 128, CAP / 128, NEXP), 256>>>(b2);
    combine_kernel<<<NTOK / 8, 256>>>(out);
}

// round 14
// speedup vs baseline: 1.5795x; 1.0150x over previous
#include <cuda_runtime.h>
#include <cuda_fp16.h>
#include <math.h>
#include <stdint.h>

// Problem constants (B=4, T=4096, H=512, E=8, K=2, F=2048, cap=5120)
#define NTOK 16384
#define HDIM 512
#define NEXP 8
#define FDIM 2048
#define CAP  5120
#define NK   32768

// ---------------- persistent device scratch (device-side refs ONLY) -----------
__device__ int   g_eidx[NK];
__device__ float g_wgt[NK];
__device__ int   g_slot[NK];
__device__ int   g_s2t[NEXP * CAP];
__device__ int   g_cnt[NEXP];
__device__ __align__(256) __half g_zero[128];

__device__ __align__(256) __half g_xhi[(size_t)NTOK * HDIM];
__device__ __align__(256) __half g_w1t_hi[(size_t)NEXP * FDIM * HDIM]; // [e][f][h]
__device__ __align__(256) __half g_w2t_hi[(size_t)NEXP * HDIM * FDIM]; // [e][h][f]
__device__ __align__(256) __half g_hhi[(size_t)NEXP * CAP * FDIM];
__device__ __align__(256) float g_eo[(size_t)NEXP * CAP * HDIM];

// ---------------- PTX helpers (portable sm_80+) -------------------------------
__device__ __forceinline__ uint32_t smem_u32(const void* p) {
    uint32_t a;
    asm("{ .reg .u64 t; cvta.to.shared.u64 t, %1; cvt.u32.u64 %0, t; }"
        : "=r"(a) : "l"(p));
    return a;
}
__device__ __forceinline__ void cp16(uint32_t dst, const void* src) {
    asm volatile("cp.async.cg.shared.global [%0], [%1], 16;"
                 :: "r"(dst), "l"(src) : "memory");
}
#define CP_COMMIT() asm volatile("cp.async.commit_group;" ::: "memory")
#define CP_WAIT(n)  asm volatile("cp.async.wait_group %0;" :: "n"(n) : "memory")

__device__ __forceinline__ void ldsm4(uint32_t r[4], uint32_t addr) {
    asm volatile("ldmatrix.sync.aligned.m8n8.x4.shared.b16 {%0,%1,%2,%3}, [%4];"
                 : "=r"(r[0]), "=r"(r[1]), "=r"(r[2]), "=r"(r[3]) : "r"(addr));
}
__device__ __forceinline__ void mma16816(float c[4], const uint32_t a[4],
                                         const uint32_t b[2]) {
    asm volatile(
        "mma.sync.aligned.m16n8k16.row.col.f32.f16.f16.f32 "
        "{%0,%1,%2,%3},{%4,%5,%6,%7},{%8,%9},{%0,%1,%2,%3};"
        : "+f"(c[0]), "+f"(c[1]), "+f"(c[2]), "+f"(c[3])
        : "r"(a[0]), "r"(a[1]), "r"(a[2]), "r"(a[3]), "r"(b[0]), "r"(b[1]));
}

// ---------------- 1) router + x->fp16 convert (fused) -------------------------
__global__ void router_kernel(const float* __restrict__ x,
                              const float* __restrict__ rw) {
    __shared__ float srw[HDIM * NEXP];
    const int tid = threadIdx.x;
    for (int i = tid; i < HDIM * NEXP; i += 256) srw[i] = rw[i];
    __syncthreads();
    const int warp = tid >> 5, lane = tid & 31;
    const int t = blockIdx.x * 8 + warp;
    const float* xr = x + (size_t)t * HDIM;

    // fp16 conversion of this token's row (vectorized)
    {
        const float4* src = (const float4*)xr;
        uint2* dst = (uint2*)(g_xhi + (size_t)t * HDIM);
#pragma unroll
        for (int j = 0; j < 4; j++) {
            float4 v = src[lane + j * 32];
            __half2 a = __halves2half2(__float2half(v.x), __float2half(v.y));
            __half2 b = __halves2half2(__float2half(v.z), __float2half(v.w));
            dst[lane + j * 32] = make_uint2(*(unsigned*)&a, *(unsigned*)&b);
        }
    }

    float acc[NEXP];
#pragma unroll
    for (int e = 0; e < NEXP; e++) acc[e] = 0.f;
#pragma unroll
    for (int j = 0; j < 16; j++) {
        int h = lane + j * 32;
        float xv = xr[h];
        const float* r = &srw[h * NEXP];
#pragma unroll
        for (int e = 0; e < NEXP; e++) acc[e] += xv * r[e];
    }
#pragma unroll
    for (int off = 16; off; off >>= 1)
#pragma unroll
        for (int e = 0; e < NEXP; e++)
            acc[e] += __shfl_down_sync(0xffffffffu, acc[e], off);
    if (lane == 0) {
        int i0 = 0;
#pragma unroll
        for (int e = 1; e < NEXP; e++) if (acc[e] > acc[i0]) i0 = e;
        int i1 = (i0 == 0) ? 1 : 0;
#pragma unroll
        for (int e = 0; e < NEXP; e++)
            if (e != i0 && acc[e] > acc[i1]) i1 = e;
        float ex = expf(acc[i1] - acc[i0]);
        float inv = 1.0f / (1.0f + ex);
        g_eidx[2 * t] = i0;  g_eidx[2 * t + 1] = i1;
        g_wgt[2 * t] = inv;  g_wgt[2 * t + 1] = ex * inv;
    }
}

// ---------------- 2) stable counting sort ------------------------------------
__global__ void assign_kernel() {
    __shared__ int sh[NEXP][1024];
    const int tid = threadIdx.x;
    for (int i = tid; i < NEXP * CAP; i += 1024) g_s2t[i] = -1;
    const int base = tid * 32;
    int lc[NEXP];
#pragma unroll
    for (int e = 0; e < NEXP; e++) lc[e] = 0;
    for (int j = 0; j < 32; j++) lc[g_eidx[base + j]]++;
#pragma unroll
    for (int e = 0; e < NEXP; e++) sh[e][tid] = lc[e];
    __syncthreads();
    for (int off = 1; off < 1024; off <<= 1) {
        int v[NEXP];
        bool p = (tid >= off);
        if (p) {
#pragma unroll
            for (int e = 0; e < NEXP; e++) v[e] = sh[e][tid - off];
        }
        __syncthreads();
        if (p) {
#pragma unroll
            for (int e = 0; e < NEXP; e++) sh[e][tid] += v[e];
        }
        __syncthreads();
    }
    if (tid == 0) {
#pragma unroll
        for (int e = 0; e < NEXP; e++) g_cnt[e] = min(sh[e][1023], CAP);
    }
    int run[NEXP];
#pragma unroll
    for (int e = 0; e < NEXP; e++) run[e] = sh[e][tid] - lc[e];
    for (int j = 0; j < 32; j++) {
        int i = base + j;
        int e = g_eidx[i];
        int s = run[e]++;
        g_slot[i] = s;
        if (s < CAP) g_s2t[e * CAP + s] = (i >> 1);
    }
}

// ---------------- 3) W [E][R][C] f32 -> fp16 transpose ------------------------
template <int WHICH>   // 1 -> g_w1t_hi (R=HDIM,C=FDIM), 2 -> g_w2t_hi (R=FDIM,C=HDIM)
__global__ void tsplit_kernel(const float* __restrict__ W) {
    constexpr int R = (WHICH == 1) ? HDIM : FDIM;
    constexpr int C = (WHICH == 1) ? FDIM : HDIM;
    __half* Oh = (WHICH == 1) ? g_w1t_hi : g_w2t_hi;

    __shared__ float t[32][33];
    const int e = blockIdx.z;
    const float* w = W + (size_t)e * R * C;
    __half* oh = Oh + (size_t)e * R * C;
    const int c0 = blockIdx.x * 32, r0 = blockIdx.y * 32;
    const int tx = threadIdx.x, ty = threadIdx.y;
#pragma unroll
    for (int j = 0; j < 4; j++)
        t[ty * 4 + j][tx] = w[(size_t)(r0 + ty * 4 + j) * C + c0 + tx];
    __syncthreads();
#pragma unroll
    for (int j = 0; j < 4; j++) {
        float v = t[tx][ty * 4 + j];
        size_t o = (size_t)(c0 + ty * 4 + j) * R + r0 + tx;
        oh[o] = __float2half(v);
    }
}

// ---------------- 4) grouped GEMM via mma.sync (plain fp16, K-chunk 32) -------
// Block tile 128x128, 8 warps (warp tile 32x64), 2-stage cp.async, static smem.
// Row pitch 64B; swizzle: kb ^= ((row>>1)&3)<<4 (proven in R11).
#define ROWB 64
#define MATB (128 * ROWB)       // 8192
#define STGB (2 * MATB)         // 16384: A, B

template <bool FIRST>
__global__ __launch_bounds__(256, 2) void moe_mma(const float* __restrict__ Bias) {
    constexpr int KD = FIRST ? HDIM : FDIM;
    constexpr int ND = FIRST ? FDIM : HDIM;
    constexpr int NC = KD / 32;

    const __half* A_g = FIRST ? g_xhi : g_hhi;
    const __half* B_g = FIRST ? g_w1t_hi : g_w2t_hi;

    const int e = blockIdx.z;
    const int m0 = blockIdx.y * 128;
    const int n0 = blockIdx.x * 128;
    if (m0 >= g_cnt[e]) return;

    __shared__ float sbias[128];
    __shared__ __align__(16) char buf[2 * STGB];
    const uint32_t sbuf = smem_u32(buf);

    const int tid = threadIdx.x, wid = tid >> 5, lane = tid & 31;
    const int warp_m = wid & 3, warp_n = wid >> 2;

    if (tid < 128) sbias[tid] = Bias[e * ND + n0 + tid];

    // ---- loader coords: row = tid>>1; two 16B chunks kb0, kb0+32 -------------
    const int lrow = tid >> 1;
    const int kb0 = (tid & 1) * 16;
    const uint32_t lsw = (((uint32_t)lrow >> 1) & 3u) << 4;
    const uint32_t dst0 = (uint32_t)lrow * ROWB + ((uint32_t)kb0 ^ lsw);
    const uint32_t dst1 = (uint32_t)lrow * ROWB + ((uint32_t)(kb0 + 32) ^ lsw);

    const char* srcA;
    bool av = true;
    if (FIRST) {
        int t = g_s2t[e * CAP + m0 + lrow];
        av = (t >= 0);
        srcA = (const char*)(A_g + (size_t)(av ? t : 0) * KD) + kb0;
    } else {
        size_t ro = ((size_t)e * CAP + m0 + lrow) * (size_t)KD;
        srcA = (const char*)(A_g + ro) + kb0;
    }
    size_t bo = ((size_t)e * ND + n0 + lrow) * (size_t)KD;
    const char* srcB = (const char*)(B_g + bo) + kb0;
    const char* zsrc = (const char*)g_zero + kb0;

    auto load_chunk = [&](int c, int s) {
        const uint32_t base = sbuf + (uint32_t)s * STGB;
        const int kB = c * 64;
        cp16(base + dst0,        av ? srcA + kB : zsrc);
        cp16(base + dst1,        av ? srcA + kB + 32 : zsrc);
        cp16(base + dst0 + MATB, srcB + kB);
        cp16(base + dst1 + MATB, srcB + kB + 32);
        CP_COMMIT();
    };

    float acc[2][8][4];
#pragma unroll
    for (int mi = 0; mi < 2; mi++)
#pragma unroll
        for (int nj = 0; nj < 8; nj++)
#pragma unroll
            for (int q = 0; q < 4; q++) acc[mi][nj][q] = 0.f;

    // ---- ldmatrix lane addressing (same swizzle as writer) -------------------
    const int fr_row = lane & 15;
    const uint32_t fr_kb = (uint32_t)((lane >> 4) * 16);
    const uint32_t rsw = (((uint32_t)fr_row >> 1) & 3u) << 4;
    const uint32_t aoff = ((uint32_t)(warp_m * 32 + fr_row)) * ROWB;
    const uint32_t boff = ((uint32_t)(warp_n * 64 + fr_row)) * ROWB + MATB;

    load_chunk(0, 0);
    for (int cc = 0; cc < NC; ++cc) {
        const int s = cc & 1;
        if (cc + 1 < NC) { load_chunk(cc + 1, s ^ 1); CP_WAIT(1); }
        else             { CP_WAIT(0); }
        __syncthreads();

        const uint32_t base = sbuf + (uint32_t)s * STGB;

#pragma unroll
        for (int kk = 0; kk < 2; kk++) {
            const uint32_t kbsw = ((uint32_t)(kk * 32) + fr_kb) ^ rsw;
            uint32_t af[2][4], bf[8][2];
#pragma unroll
            for (int mi = 0; mi < 2; mi++)
                ldsm4(af[mi], base + aoff + (uint32_t)mi * 16 * ROWB + kbsw);
#pragma unroll
            for (int j = 0; j < 4; j++) {
                uint32_t t4[4];
                ldsm4(t4, base + boff + (uint32_t)j * 16 * ROWB + kbsw);
                bf[2 * j][0] = t4[0];     bf[2 * j][1] = t4[2];
                bf[2 * j + 1][0] = t4[1]; bf[2 * j + 1][1] = t4[3];
            }
#pragma unroll
            for (int mi = 0; mi < 2; mi++)
#pragma unroll
                for (int nj = 0; nj < 8; nj++)
                    mma16816(acc[mi][nj], af[mi], bf[nj]);
        }
        __syncthreads();
    }

    // ---- epilogue ----
    const int rbase = m0 + warp_m * 32 + (lane >> 2);
    const int cbase = warp_n * 64 + (lane & 3) * 2;
#pragma unroll
    for (int mi = 0; mi < 2; mi++) {
#pragma unroll
        for (int nj = 0; nj < 8; nj++) {
            int col = cbase + nj * 8;
            float bia0 = sbias[col], bia1 = sbias[col + 1];
#pragma unroll
            for (int hh = 0; hh < 2; hh++) {
                int r = rbase + mi * 16 + hh * 8;
                float z0 = acc[mi][nj][2 * hh] + bia0;
                float z1 = acc[mi][nj][2 * hh + 1] + bia1;
                if (FIRST) {
                    float u0 = 0.7978845608028654f * (z0 + 0.044715f * z0 * z0 * z0);
                    float u1 = 0.7978845608028654f * (z1 + 0.044715f * z1 * z1 * z1);
                    float g0 = 0.5f * z0 * (1.0f + tanhf(u0));
                    float g1 = 0.5f * z1 * (1.0f + tanhf(u1));
                    __half2 hp = __halves2half2(__float2half(g0), __float2half(g1));
                    size_t off = ((size_t)e * CAP + r) * FDIM + n0 + col;
                    *(unsigned*)(g_hhi + off) = *(unsigned*)&hp;
                } else {
                    size_t off = ((size_t)e * CAP + r) * HDIM + n0 + col;
                    *(float2*)(g_eo + off) = make_float2(z0, z1);
                }
            }
        }
    }
}

// ---------------- 5) combine ---------------------------------------------------
__global__ void combine_kernel(float* __restrict__ out) {
    const int tid = threadIdx.x;
    const int warp = tid >> 5, lane = tid & 31;
    const int t = blockIdx.x * 8 + warp;
    float4 acc[4];
#pragma unroll
    for (int q = 0; q < 4; q++) acc[q] = make_float4(0.f, 0.f, 0.f, 0.f);
#pragma unroll
    for (int k = 0; k < 2; k++) {
        int s = g_slot[2 * t + k];
        if (s < CAP) {
            int e = g_eidx[2 * t + k];
            float w = g_wgt[2 * t + k];
            const float4* src = (const float4*)(g_eo + ((size_t)e * CAP + s) * HDIM);
#pragma unroll
            for (int q = 0; q < 4; q++) {
                float4 v = src[lane + q * 32];
                acc[q].x += w * v.x; acc[q].y += w * v.y;
                acc[q].z += w * v.z; acc[q].w += w * v.w;
            }
        }
    }
    float4* o = (float4*)(out + (size_t)t * HDIM);
#pragma unroll
    for (int q = 0; q < 4; q++) o[lane + q * 32] = acc[q];
}

// ---------------- launch -------------------------------------------------------
extern "C" void kernel_launch(void* const* d_in, const int* in_sizes, int n_in,
                              void* d_out, int out_size) {
    const float* x  = (const float*)d_in[0];
    const float* rw = (const float*)d_in[1];
    const float* w1 = (const float*)d_in[2];
    const float* b1 = (const float*)d_in[3];
    const float* w2 = (const float*)d_in[4];
    const float* b2 = (const float*)d_in[5];
    float* out = (float*)d_out;

    router_kernel<<<NTOK / 8, 256>>>(x, rw);
    assign_kernel<<<1, 1024>>>();
    tsplit_kernel<1><<<dim3(FDIM / 32, HDIM / 32, NEXP), dim3(32, 8)>>>(w1);
    tsplit_kernel<2><<<dim3(HDIM / 32, FDIM / 32, NEXP), dim3(32, 8)>>>(w2);
    moe_mma<true><<<dim3(FDIM / 128, CAP / 128, NEXP), 256>>>(b1);
    moe_mma<false><<<dim3(HDIM / 128, CAP / 128, NEXP), 256>>>(b2);
    combine_kernel<<<NTOK / 8, 256>>>(out);
}

// round 15
// speedup vs baseline: 1.6429x; 1.0401x over previous
#include <cuda_runtime.h>
#include <cuda_fp16.h>
#include <math.h>
#include <stdint.h>

// Problem constants (B=4, T=4096, H=512, E=8, K=2, F=2048, cap=5120)
#define NTOK 16384
#define HDIM 512
#define NEXP 8
#define FDIM 2048
#define CAP  5120
#define NK   32768

// ---------------- persistent device scratch (device-side refs ONLY) -----------
__device__ int   g_eidx[NK];
__device__ float g_wgt[NK];
__device__ int   g_slot[NK];
__device__ int   g_s2t[NEXP * CAP];
__device__ int   g_cnt[NEXP];
__device__ __align__(256) __half g_zero[128];

__device__ __align__(256) __half g_xhi[(size_t)NTOK * HDIM];
__device__ __align__(256) __half g_w1t_hi[(size_t)NEXP * FDIM * HDIM]; // [e][f][h]
__device__ __align__(256) __half g_w2t_hi[(size_t)NEXP * HDIM * FDIM]; // [e][h][f]
__device__ __align__(256) __half g_hhi[(size_t)NEXP * CAP * FDIM];
__device__ __align__(256) __half g_eo[(size_t)NEXP * CAP * HDIM];

// ---------------- PTX helpers (portable sm_80+) -------------------------------
__device__ __forceinline__ uint32_t smem_u32(const void* p) {
    uint32_t a;
    asm("{ .reg .u64 t; cvta.to.shared.u64 t, %1; cvt.u32.u64 %0, t; }"
        : "=r"(a) : "l"(p));
    return a;
}
__device__ __forceinline__ void cp16(uint32_t dst, const void* src) {
    asm volatile("cp.async.cg.shared.global [%0], [%1], 16;"
                 :: "r"(dst), "l"(src) : "memory");
}
#define CP_COMMIT() asm volatile("cp.async.commit_group;" ::: "memory")
#define CP_WAIT(n)  asm volatile("cp.async.wait_group %0;" :: "n"(n) : "memory")

__device__ __forceinline__ void ldsm4(uint32_t r[4], uint32_t addr) {
    asm volatile("ldmatrix.sync.aligned.m8n8.x4.shared.b16 {%0,%1,%2,%3}, [%4];"
                 : "=r"(r[0]), "=r"(r[1]), "=r"(r[2]), "=r"(r[3]) : "r"(addr));
}
__device__ __forceinline__ void mma16816(float c[4], const uint32_t a[4],
                                         const uint32_t b[2]) {
    asm volatile(
        "mma.sync.aligned.m16n8k16.row.col.f32.f16.f16.f32 "
        "{%0,%1,%2,%3},{%4,%5,%6,%7},{%8,%9},{%0,%1,%2,%3};"
        : "+f"(c[0]), "+f"(c[1]), "+f"(c[2]), "+f"(c[3])
        : "r"(a[0]), "r"(a[1]), "r"(a[2]), "r"(a[3]), "r"(b[0]), "r"(b[1]));
}
__device__ __forceinline__ float tanh_fast(float u) {
    float r;
    asm("tanh.approx.f32 %0, %1;" : "=f"(r) : "f"(u));
    return r;
}
// gelu(z) = 0.5 z (1 + tanh(0.7978845608 (z + 0.044715 z^3)))
__device__ __forceinline__ float gelu_fast(float z) {
    float zz = z * z;
    float u = z * fmaf(0.035677408136f, zz, 0.7978845608028654f);
    float hz = 0.5f * z;
    return fmaf(hz, tanh_fast(u), hz);
}

// ---------------- 1) router + x->fp16 convert (fused) -------------------------
__global__ void router_kernel(const float* __restrict__ x,
                              const float* __restrict__ rw) {
    __shared__ float srw[HDIM * NEXP];
    const int tid = threadIdx.x;
    for (int i = tid; i < HDIM * NEXP; i += 256) srw[i] = rw[i];
    __syncthreads();
    const int warp = tid >> 5, lane = tid & 31;
    const int t = blockIdx.x * 8 + warp;
    const float* xr = x + (size_t)t * HDIM;

    {
        const float4* src = (const float4*)xr;
        uint2* dst = (uint2*)(g_xhi + (size_t)t * HDIM);
#pragma unroll
        for (int j = 0; j < 4; j++) {
            float4 v = src[lane + j * 32];
            __half2 a = __halves2half2(__float2half(v.x), __float2half(v.y));
            __half2 b = __halves2half2(__float2half(v.z), __float2half(v.w));
            dst[lane + j * 32] = make_uint2(*(unsigned*)&a, *(unsigned*)&b);
        }
    }

    float acc[NEXP];
#pragma unroll
    for (int e = 0; e < NEXP; e++) acc[e] = 0.f;
#pragma unroll
    for (int j = 0; j < 16; j++) {
        int h = lane + j * 32;
        float xv = xr[h];
        const float* r = &srw[h * NEXP];
#pragma unroll
        for (int e = 0; e < NEXP; e++) acc[e] += xv * r[e];
    }
#pragma unroll
    for (int off = 16; off; off >>= 1)
#pragma unroll
        for (int e = 0; e < NEXP; e++)
            acc[e] += __shfl_down_sync(0xffffffffu, acc[e], off);
    if (lane == 0) {
        int i0 = 0;
#pragma unroll
        for (int e = 1; e < NEXP; e++) if (acc[e] > acc[i0]) i0 = e;
        int i1 = (i0 == 0) ? 1 : 0;
#pragma unroll
        for (int e = 0; e < NEXP; e++)
            if (e != i0 && acc[e] > acc[i1]) i1 = e;
        float ex = expf(acc[i1] - acc[i0]);
        float inv = 1.0f / (1.0f + ex);
        g_eidx[2 * t] = i0;  g_eidx[2 * t + 1] = i1;
        g_wgt[2 * t] = inv;  g_wgt[2 * t + 1] = ex * inv;
    }
}

// ---------------- 2) stable counting sort ------------------------------------
__global__ void assign_kernel() {
    __shared__ int sh[NEXP][1024];
    const int tid = threadIdx.x;
    for (int i = tid; i < NEXP * CAP; i += 1024) g_s2t[i] = -1;
    const int base = tid * 32;
    int lc[NEXP];
#pragma unroll
    for (int e = 0; e < NEXP; e++) lc[e] = 0;
    for (int j = 0; j < 32; j++) lc[g_eidx[base + j]]++;
#pragma unroll
    for (int e = 0; e < NEXP; e++) sh[e][tid] = lc[e];
    __syncthreads();
    for (int off = 1; off < 1024; off <<= 1) {
        int v[NEXP];
        bool p = (tid >= off);
        if (p) {
#pragma unroll
            for (int e = 0; e < NEXP; e++) v[e] = sh[e][tid - off];
        }
        __syncthreads();
        if (p) {
#pragma unroll
            for (int e = 0; e < NEXP; e++) sh[e][tid] += v[e];
        }
        __syncthreads();
    }
    if (tid == 0) {
#pragma unroll
        for (int e = 0; e < NEXP; e++) g_cnt[e] = min(sh[e][1023], CAP);
    }
    int run[NEXP];
#pragma unroll
    for (int e = 0; e < NEXP; e++) run[e] = sh[e][tid] - lc[e];
    for (int j = 0; j < 32; j++) {
        int i = base + j;
        int e = g_eidx[i];
        int s = run[e]++;
        g_slot[i] = s;
        if (s < CAP) g_s2t[e * CAP + s] = (i >> 1);
    }
}

// ---------------- 3) W [E][R][C] f32 -> fp16 transpose ------------------------
template <int WHICH>   // 1 -> g_w1t_hi (R=HDIM,C=FDIM), 2 -> g_w2t_hi (R=FDIM,C=HDIM)
__global__ void tsplit_kernel(const float* __restrict__ W) {
    constexpr int R = (WHICH == 1) ? HDIM : FDIM;
    constexpr int C = (WHICH == 1) ? FDIM : HDIM;
    __half* Oh = (WHICH == 1) ? g_w1t_hi : g_w2t_hi;

    __shared__ float t[32][33];
    const int e = blockIdx.z;
    const float* w = W + (size_t)e * R * C;
    __half* oh = Oh + (size_t)e * R * C;
    const int c0 = blockIdx.x * 32, r0 = blockIdx.y * 32;
    const int tx = threadIdx.x, ty = threadIdx.y;
#pragma unroll
    for (int j = 0; j < 4; j++)
        t[ty * 4 + j][tx] = w[(size_t)(r0 + ty * 4 + j) * C + c0 + tx];
    __syncthreads();
#pragma unroll
    for (int j = 0; j < 4; j++) {
        float v = t[tx][ty * 4 + j];
        size_t o = (size_t)(c0 + ty * 4 + j) * R + r0 + tx;
        oh[o] = __float2half(v);
    }
}

// ---------------- 4) grouped GEMM via mma.sync (plain fp16, K-chunk 32) -------
#define ROWB 64
#define MATB (128 * ROWB)       // 8192
#define STGB (2 * MATB)         // 16384: A, B

template <bool FIRST>
__global__ __launch_bounds__(256, 2) void moe_mma(const float* __restrict__ Bias) {
    constexpr int KD = FIRST ? HDIM : FDIM;
    constexpr int ND = FIRST ? FDIM : HDIM;
    constexpr int NC = KD / 32;

    const __half* A_g = FIRST ? g_xhi : g_hhi;
    const __half* B_g = FIRST ? g_w1t_hi : g_w2t_hi;

    const int e = blockIdx.z;
    const int m0 = blockIdx.y * 128;
    const int n0 = blockIdx.x * 128;
    if (m0 >= g_cnt[e]) return;

    __shared__ float sbias[128];
    __shared__ __align__(16) char buf[2 * STGB];
    const uint32_t sbuf = smem_u32(buf);

    const int tid = threadIdx.x, wid = tid >> 5, lane = tid & 31;
    const int warp_m = wid & 3, warp_n = wid >> 2;

    if (tid < 128) sbias[tid] = Bias[e * ND + n0 + tid];

    const int lrow = tid >> 1;
    const int kb0 = (tid & 1) * 16;
    const uint32_t lsw = (((uint32_t)lrow >> 1) & 3u) << 4;
    const uint32_t dst0 = (uint32_t)lrow * ROWB + ((uint32_t)kb0 ^ lsw);
    const uint32_t dst1 = (uint32_t)lrow * ROWB + ((uint32_t)(kb0 + 32) ^ lsw);

    const char* srcA;
    bool av = true;
    if (FIRST) {
        int t = g_s2t[e * CAP + m0 + lrow];
        av = (t >= 0);
        srcA = (const char*)(A_g + (size_t)(av ? t : 0) * KD) + kb0;
    } else {
        size_t ro = ((size_t)e * CAP + m0 + lrow) * (size_t)KD;
        srcA = (const char*)(A_g + ro) + kb0;
    }
    size_t bo = ((size_t)e * ND + n0 + lrow) * (size_t)KD;
    const char* srcB = (const char*)(B_g + bo) + kb0;
    const char* zsrc = (const char*)g_zero + kb0;

    auto load_chunk = [&](int c, int s) {
        const uint32_t base = sbuf + (uint32_t)s * STGB;
        const int kB = c * 64;
        cp16(base + dst0,        av ? srcA + kB : zsrc);
        cp16(base + dst1,        av ? srcA + kB + 32 : zsrc);
        cp16(base + dst0 + MATB, srcB + kB);
        cp16(base + dst1 + MATB, srcB + kB + 32);
        CP_COMMIT();
    };

    float acc[2][8][4];
#pragma unroll
    for (int mi = 0; mi < 2; mi++)
#pragma unroll
        for (int nj = 0; nj < 8; nj++)
#pragma unroll
            for (int q = 0; q < 4; q++) acc[mi][nj][q] = 0.f;

    const int fr_row = lane & 15;
    const uint32_t fr_kb = (uint32_t)((lane >> 4) * 16);
    const uint32_t rsw = (((uint32_t)fr_row >> 1) & 3u) << 4;
    const uint32_t aoff = ((uint32_t)(warp_m * 32 + fr_row)) * ROWB;
    const uint32_t boff = ((uint32_t)(warp_n * 64 + fr_row)) * ROWB + MATB;

    load_chunk(0, 0);
    for (int cc = 0; cc < NC; ++cc) {
        const int s = cc & 1;
        if (cc + 1 < NC) { load_chunk(cc + 1, s ^ 1); CP_WAIT(1); }
        else             { CP_WAIT(0); }
        __syncthreads();

        const uint32_t base = sbuf + (uint32_t)s * STGB;

#pragma unroll
        for (int kk = 0; kk < 2; kk++) {
            const uint32_t kbsw = ((uint32_t)(kk * 32) + fr_kb) ^ rsw;
            uint32_t af[2][4], bf[8][2];
#pragma unroll
            for (int mi = 0; mi < 2; mi++)
                ldsm4(af[mi], base + aoff + (uint32_t)mi * 16 * ROWB + kbsw);
#pragma unroll
            for (int j = 0; j < 4; j++) {
                uint32_t t4[4];
                ldsm4(t4, base + boff + (uint32_t)j * 16 * ROWB + kbsw);
                bf[2 * j][0] = t4[0];     bf[2 * j][1] = t4[2];
                bf[2 * j + 1][0] = t4[1]; bf[2 * j + 1][1] = t4[3];
            }
#pragma unroll
            for (int mi = 0; mi < 2; mi++)
#pragma unroll
                for (int nj = 0; nj < 8; nj++)
                    mma16816(acc[mi][nj], af[mi], bf[nj]);
        }
        __syncthreads();
    }

    // ---- epilogue ----
    const int rbase = m0 + warp_m * 32 + (lane >> 2);
    const int cbase = warp_n * 64 + (lane & 3) * 2;
#pragma unroll
    for (int mi = 0; mi < 2; mi++) {
#pragma unroll
        for (int nj = 0; nj < 8; nj++) {
            int col = cbase + nj * 8;
            float bia0 = sbias[col], bia1 = sbias[col + 1];
#pragma unroll
            for (int hh = 0; hh < 2; hh++) {
                int r = rbase + mi * 16 + hh * 8;
                float z0 = acc[mi][nj][2 * hh] + bia0;
                float z1 = acc[mi][nj][2 * hh + 1] + bia1;
                if (FIRST) {
                    float g0 = gelu_fast(z0);
                    float g1 = gelu_fast(z1);
                    __half2 hp = __halves2half2(__float2half(g0), __float2half(g1));
                    size_t off = ((size_t)e * CAP + r) * FDIM + n0 + col;
                    *(unsigned*)(g_hhi + off) = *(unsigned*)&hp;
                } else {
                    __half2 hp = __halves2half2(__float2half(z0), __float2half(z1));
                    size_t off = ((size_t)e * CAP + r) * HDIM + n0 + col;
                    *(unsigned*)(g_eo + off) = *(unsigned*)&hp;
                }
            }
        }
    }
}

// ---------------- 5) combine (fp16 expert outputs -> fp32 tokens) -------------
__global__ void combine_kernel(float* __restrict__ out) {
    const int tid = threadIdx.x;
    const int warp = tid >> 5, lane = tid & 31;
    const int t = blockIdx.x * 8 + warp;
    float acc[16];
#pragma unroll
    for (int q = 0; q < 16; q++) acc[q] = 0.f;

#pragma unroll
    for (int k = 0; k < 2; k++) {
        int s = g_slot[2 * t + k];
        if (s < CAP) {
            int e = g_eidx[2 * t + k];
            float w = g_wgt[2 * t + k];
            const uint4* src = (const uint4*)(g_eo + ((size_t)e * CAP + s) * HDIM);
#pragma unroll
            for (int q = 0; q < 2; q++) {
                uint4 v = src[lane + q * 32];
                const __half2* h2 = (const __half2*)&v;
#pragma unroll
                for (int j = 0; j < 4; j++) {
                    float2 f = __half22float2(h2[j]);
                    acc[q * 8 + j * 2]     += w * f.x;
                    acc[q * 8 + j * 2 + 1] += w * f.y;
                }
            }
        }
    }
    float4* o = (float4*)(out + (size_t)t * HDIM);
#pragma unroll
    for (int q = 0; q < 2; q++) {
        o[(lane + q * 32) * 2] =
            make_float4(acc[q * 8 + 0], acc[q * 8 + 1], acc[q * 8 + 2], acc[q * 8 + 3]);
        o[(lane + q * 32) * 2 + 1] =
            make_float4(acc[q * 8 + 4], acc[q * 8 + 5], acc[q * 8 + 6], acc[q * 8 + 7]);
    }
}

// ---------------- launch -------------------------------------------------------
extern "C" void kernel_launch(void* const* d_in, const int* in_sizes, int n_in,
                              void* d_out, int out_size) {
    const float* x  = (const float*)d_in[0];
    const float* rw = (const float*)d_in[1];
    const float* w1 = (const float*)d_in[2];
    const float* b1 = (const float*)d_in[3];
    const float* w2 = (const float*)d_in[4];
    const float* b2 = (const float*)d_in[5];
    float* out = (float*)d_out;

    router_kernel<<<NTOK / 8, 256>>>(x, rw);
    assign_kernel<<<1, 1024>>>();
    tsplit_kernel<1><<<dim3(FDIM / 32, HDIM / 32, NEXP), dim3(32, 8)>>>(w1);
    tsplit_kernel<2><<<dim3(HDIM / 32, FDIM / 32, NEXP), dim3(32, 8)>>>(w2);
    moe_mma<true><<<dim3(FDIM / 128, CAP / 128, NEXP), 256>>>(b1);
    moe_mma<false><<<dim3(HDIM / 128, CAP / 128, NEXP), 256>>>(b2);
    combine_kernel<<<NTOK / 8, 256>>>(out);
}

// round 16
// speedup vs baseline: 1.7263x; 1.0508x over previous
#include <cuda_runtime.h>
#include <cuda_fp16.h>
#include <math.h>
#include <stdint.h>

// Problem constants (B=4, T=4096, H=512, E=8, K=2, F=2048, cap=5120)
#define NTOK 16384
#define HDIM 512
#define NEXP 8
#define FDIM 2048
#define CAP  5120
#define NK   32768

// ---------------- persistent device scratch (device-side refs ONLY) -----------
__device__ int   g_eidx[NK];
__device__ float g_wgt[NK];
__device__ int   g_slot[NK];
__device__ int   g_s2t[NEXP * CAP];
__device__ int   g_cnt[NEXP];
__device__ __align__(256) __half g_zero[128];

__device__ __align__(256) __half g_xhi[(size_t)NTOK * HDIM];
__device__ __align__(256) __half g_w1t_hi[(size_t)NEXP * FDIM * HDIM]; // [e][f][h]
__device__ __align__(256) __half g_w2t_hi[(size_t)NEXP * HDIM * FDIM]; // [e][h][f]
__device__ __align__(256) __half g_hhi[(size_t)NEXP * CAP * FDIM];
__device__ __align__(256) __half g_eo[(size_t)NEXP * CAP * HDIM];

// ---------------- PTX helpers (portable sm_80+) -------------------------------
__device__ __forceinline__ uint32_t smem_u32(const void* p) {
    uint32_t a;
    asm("{ .reg .u64 t; cvta.to.shared.u64 t, %1; cvt.u32.u64 %0, t; }"
        : "=r"(a) : "l"(p));
    return a;
}
__device__ __forceinline__ void cp16(uint32_t dst, const void* src) {
    asm volatile("cp.async.cg.shared.global [%0], [%1], 16;"
                 :: "r"(dst), "l"(src) : "memory");
}
#define CP_COMMIT() asm volatile("cp.async.commit_group;" ::: "memory")
#define CP_WAIT(n)  asm volatile("cp.async.wait_group %0;" :: "n"(n) : "memory")

__device__ __forceinline__ void ldsm4(uint32_t r[4], uint32_t addr) {
    asm volatile("ldmatrix.sync.aligned.m8n8.x4.shared.b16 {%0,%1,%2,%3}, [%4];"
                 : "=r"(r[0]), "=r"(r[1]), "=r"(r[2]), "=r"(r[3]) : "r"(addr));
}
__device__ __forceinline__ void mma16816(float c[4], const uint32_t a[4],
                                         const uint32_t b[2]) {
    asm volatile(
        "mma.sync.aligned.m16n8k16.row.col.f32.f16.f16.f32 "
        "{%0,%1,%2,%3},{%4,%5,%6,%7},{%8,%9},{%0,%1,%2,%3};"
        : "+f"(c[0]), "+f"(c[1]), "+f"(c[2]), "+f"(c[3])
        : "r"(a[0]), "r"(a[1]), "r"(a[2]), "r"(a[3]), "r"(b[0]), "r"(b[1]));
}
__device__ __forceinline__ float tanh_fast(float u) {
    float r;
    asm("tanh.approx.f32 %0, %1;" : "=f"(r) : "f"(u));
    return r;
}
__device__ __forceinline__ float gelu_fast(float z) {
    float zz = z * z;
    float u = z * fmaf(0.035677408136f, zz, 0.7978845608028654f);
    float hz = 0.5f * z;
    return fmaf(hz, tanh_fast(u), hz);
}

// ---------------- 1) router + x->fp16 convert (fused) -------------------------
__global__ void router_kernel(const float* __restrict__ x,
                              const float* __restrict__ rw) {
    __shared__ float srw[HDIM * NEXP];
    const int tid = threadIdx.x;
    for (int i = tid; i < HDIM * NEXP; i += 256) srw[i] = rw[i];
    __syncthreads();
    const int warp = tid >> 5, lane = tid & 31;
    const int t = blockIdx.x * 8 + warp;
    const float* xr = x + (size_t)t * HDIM;

    {
        const float4* src = (const float4*)xr;
        uint2* dst = (uint2*)(g_xhi + (size_t)t * HDIM);
#pragma unroll
        for (int j = 0; j < 4; j++) {
            float4 v = src[lane + j * 32];
            __half2 a = __halves2half2(__float2half(v.x), __float2half(v.y));
            __half2 b = __halves2half2(__float2half(v.z), __float2half(v.w));
            dst[lane + j * 32] = make_uint2(*(unsigned*)&a, *(unsigned*)&b);
        }
    }

    float acc[NEXP];
#pragma unroll
    for (int e = 0; e < NEXP; e++) acc[e] = 0.f;
#pragma unroll
    for (int j = 0; j < 16; j++) {
        int h = lane + j * 32;
        float xv = xr[h];
        const float* r = &srw[h * NEXP];
#pragma unroll
        for (int e = 0; e < NEXP; e++) acc[e] += xv * r[e];
    }
#pragma unroll
    for (int off = 16; off; off >>= 1)
#pragma unroll
        for (int e = 0; e < NEXP; e++)
            acc[e] += __shfl_down_sync(0xffffffffu, acc[e], off);
    if (lane == 0) {
        int i0 = 0;
#pragma unroll
        for (int e = 1; e < NEXP; e++) if (acc[e] > acc[i0]) i0 = e;
        int i1 = (i0 == 0) ? 1 : 0;
#pragma unroll
        for (int e = 0; e < NEXP; e++)
            if (e != i0 && acc[e] > acc[i1]) i1 = e;
        float ex = expf(acc[i1] - acc[i0]);
        float inv = 1.0f / (1.0f + ex);
        g_eidx[2 * t] = i0;  g_eidx[2 * t + 1] = i1;
        g_wgt[2 * t] = inv;  g_wgt[2 * t + 1] = ex * inv;
    }
}

// ---------------- 2) stable counting sort ------------------------------------
__global__ void assign_kernel() {
    __shared__ int sh[NEXP][1024];
    const int tid = threadIdx.x;
    for (int i = tid; i < NEXP * CAP; i += 1024) g_s2t[i] = -1;
    const int base = tid * 32;
    int lc[NEXP];
#pragma unroll
    for (int e = 0; e < NEXP; e++) lc[e] = 0;
    for (int j = 0; j < 32; j++) lc[g_eidx[base + j]]++;
#pragma unroll
    for (int e = 0; e < NEXP; e++) sh[e][tid] = lc[e];
    __syncthreads();
    for (int off = 1; off < 1024; off <<= 1) {
        int v[NEXP];
        bool p = (tid >= off);
        if (p) {
#pragma unroll
            for (int e = 0; e < NEXP; e++) v[e] = sh[e][tid - off];
        }
        __syncthreads();
        if (p) {
#pragma unroll
            for (int e = 0; e < NEXP; e++) sh[e][tid] += v[e];
        }
        __syncthreads();
    }
    if (tid == 0) {
#pragma unroll
        for (int e = 0; e < NEXP; e++) g_cnt[e] = min(sh[e][1023], CAP);
    }
    int run[NEXP];
#pragma unroll
    for (int e = 0; e < NEXP; e++) run[e] = sh[e][tid] - lc[e];
    for (int j = 0; j < 32; j++) {
        int i = base + j;
        int e = g_eidx[i];
        int s = run[e]++;
        g_slot[i] = s;
        if (s < CAP) g_s2t[e * CAP + s] = (i >> 1);
    }
}

// ---------------- 3) fused weight transpose: w1 AND w2 in one launch ----------
// grid = (64, 16, 16); z < 8: w1 expert z; z >= 8: w2 expert z-8.
// w1: R=HDIM(512) C=FDIM(2048): r-blocks 16 (by), c-blocks 64 (bx)
// w2: R=FDIM(2048) C=HDIM(512): r-blocks 64 (by + 16*(bx>>4)), c-blocks 16 (bx&15)
__global__ void tsplit_kernel(const float* __restrict__ W1,
                              const float* __restrict__ W2) {
    __shared__ float t[32][33];
    const int z = blockIdx.z;
    const bool is2 = (z >= 8);
    const int e = is2 ? z - 8 : z;
    const int R = is2 ? FDIM : HDIM;
    const int C = is2 ? HDIM : FDIM;
    const float* w = (is2 ? W2 : W1) + (size_t)e * R * C;
    __half* oh = (is2 ? g_w2t_hi : g_w1t_hi) + (size_t)e * R * C;

    int c0, r0;
    if (is2) { c0 = (blockIdx.x & 15) * 32; r0 = (blockIdx.y + 16 * (blockIdx.x >> 4)) * 32; }
    else     { c0 = blockIdx.x * 32;        r0 = blockIdx.y * 32; }

    const int tx = threadIdx.x, ty = threadIdx.y;
#pragma unroll
    for (int j = 0; j < 4; j++)
        t[ty * 4 + j][tx] = w[(size_t)(r0 + ty * 4 + j) * C + c0 + tx];
    __syncthreads();
#pragma unroll
    for (int j = 0; j < 4; j++) {
        float v = t[tx][ty * 4 + j];
        size_t o = (size_t)(c0 + ty * 4 + j) * R + r0 + tx;
        oh[o] = __float2half(v);
    }
}

// ---------------- 4) grouped GEMM via mma.sync (plain fp16, K-chunk 32) -------
// ONE barrier per chunk: load(cc+1) issued after the sync that drains stage
// (cc+1)&1's readers from iteration cc-1.
#define ROWB 64
#define MATB (128 * ROWB)       // 8192
#define STGB (2 * MATB)         // 16384: A, B

template <bool FIRST>
__global__ __launch_bounds__(256, 2) void moe_mma(const float* __restrict__ Bias) {
    constexpr int KD = FIRST ? HDIM : FDIM;
    constexpr int ND = FIRST ? FDIM : HDIM;
    constexpr int NC = KD / 32;

    const __half* A_g = FIRST ? g_xhi : g_hhi;
    const __half* B_g = FIRST ? g_w1t_hi : g_w2t_hi;

    const int e = blockIdx.z;
    const int m0 = blockIdx.y * 128;
    const int n0 = blockIdx.x * 128;
    if (m0 >= g_cnt[e]) return;

    __shared__ float sbias[128];
    __shared__ __align__(16) char buf[2 * STGB];
    const uint32_t sbuf = smem_u32(buf);

    const int tid = threadIdx.x, wid = tid >> 5, lane = tid & 31;
    const int warp_m = wid & 3, warp_n = wid >> 2;

    if (tid < 128) sbias[tid] = Bias[e * ND + n0 + tid];

    const int lrow = tid >> 1;
    const int kb0 = (tid & 1) * 16;
    const uint32_t lsw = (((uint32_t)lrow >> 1) & 3u) << 4;
    const uint32_t dst0 = (uint32_t)lrow * ROWB + ((uint32_t)kb0 ^ lsw);
    const uint32_t dst1 = (uint32_t)lrow * ROWB + ((uint32_t)(kb0 + 32) ^ lsw);

    const char* srcA;
    bool av = true;
    if (FIRST) {
        int t = g_s2t[e * CAP + m0 + lrow];
        av = (t >= 0);
        srcA = (const char*)(A_g + (size_t)(av ? t : 0) * KD) + kb0;
    } else {
        size_t ro = ((size_t)e * CAP + m0 + lrow) * (size_t)KD;
        srcA = (const char*)(A_g + ro) + kb0;
    }
    size_t bo = ((size_t)e * ND + n0 + lrow) * (size_t)KD;
    const char* srcB = (const char*)(B_g + bo) + kb0;
    const char* zsrc = (const char*)g_zero + kb0;

    auto load_chunk = [&](int c, int s) {
        const uint32_t base = sbuf + (uint32_t)s * STGB;
        const int kB = c * 64;
        cp16(base + dst0,        av ? srcA + kB : zsrc);
        cp16(base + dst1,        av ? srcA + kB + 32 : zsrc);
        cp16(base + dst0 + MATB, srcB + kB);
        cp16(base + dst1 + MATB, srcB + kB + 32);
        CP_COMMIT();
    };

    float acc[2][8][4];
#pragma unroll
    for (int mi = 0; mi < 2; mi++)
#pragma unroll
        for (int nj = 0; nj < 8; nj++)
#pragma unroll
            for (int q = 0; q < 4; q++) acc[mi][nj][q] = 0.f;

    const int fr_row = lane & 15;
    const uint32_t fr_kb = (uint32_t)((lane >> 4) * 16);
    const uint32_t rsw = (((uint32_t)fr_row >> 1) & 3u) << 4;
    const uint32_t aoff = ((uint32_t)(warp_m * 32 + fr_row)) * ROWB;
    const uint32_t boff = ((uint32_t)(warp_n * 64 + fr_row)) * ROWB + MATB;

    load_chunk(0, 0);
    for (int cc = 0; cc < NC; ++cc) {
        const int s = cc & 1;
        CP_WAIT(0);            // load of chunk cc complete (only group in flight)
        __syncthreads();       // all warps done reading stage s^1 (iter cc-1)
        if (cc + 1 < NC) load_chunk(cc + 1, s ^ 1);

        const uint32_t base = sbuf + (uint32_t)s * STGB;
#pragma unroll
        for (int kk = 0; kk < 2; kk++) {
            const uint32_t kbsw = ((uint32_t)(kk * 32) + fr_kb) ^ rsw;
            uint32_t af[2][4], bf[8][2];
#pragma unroll
            for (int mi = 0; mi < 2; mi++)
                ldsm4(af[mi], base + aoff + (uint32_t)mi * 16 * ROWB + kbsw);
#pragma unroll
            for (int j = 0; j < 4; j++) {
                uint32_t t4[4];
                ldsm4(t4, base + boff + (uint32_t)j * 16 * ROWB + kbsw);
                bf[2 * j][0] = t4[0];     bf[2 * j][1] = t4[2];
                bf[2 * j + 1][0] = t4[1]; bf[2 * j + 1][1] = t4[3];
            }
#pragma unroll
            for (int mi = 0; mi < 2; mi++)
#pragma unroll
                for (int nj = 0; nj < 8; nj++)
                    mma16816(acc[mi][nj], af[mi], bf[nj]);
        }
    }

    // ---- epilogue ----
    const int rbase = m0 + warp_m * 32 + (lane >> 2);
    const int cbase = warp_n * 64 + (lane & 3) * 2;
#pragma unroll
    for (int mi = 0; mi < 2; mi++) {
#pragma unroll
        for (int nj = 0; nj < 8; nj++) {
            int col = cbase + nj * 8;
            float bia0 = sbias[col], bia1 = sbias[col + 1];
#pragma unroll
            for (int hh = 0; hh < 2; hh++) {
                int r = rbase + mi * 16 + hh * 8;
                float z0 = acc[mi][nj][2 * hh] + bia0;
                float z1 = acc[mi][nj][2 * hh + 1] + bia1;
                if (FIRST) {
                    float g0 = gelu_fast(z0);
                    float g1 = gelu_fast(z1);
                    __half2 hp = __halves2half2(__float2half(g0), __float2half(g1));
                    size_t off = ((size_t)e * CAP + r) * FDIM + n0 + col;
                    *(unsigned*)(g_hhi + off) = *(unsigned*)&hp;
                } else {
                    __half2 hp = __halves2half2(__float2half(z0), __float2half(z1));
                    size_t off = ((size_t)e * CAP + r) * HDIM + n0 + col;
                    *(unsigned*)(g_eo + off) = *(unsigned*)&hp;
                }
            }
        }
    }
}

// ---------------- 5) combine (fp16 expert outputs -> fp32 tokens) -------------
__global__ void combine_kernel(float* __restrict__ out) {
    const int tid = threadIdx.x;
    const int warp = tid >> 5, lane = tid & 31;
    const int t = blockIdx.x * 8 + warp;
    float acc[16];
#pragma unroll
    for (int q = 0; q < 16; q++) acc[q] = 0.f;

#pragma unroll
    for (int k = 0; k < 2; k++) {
        int s = g_slot[2 * t + k];
        if (s < CAP) {
            int e = g_eidx[2 * t + k];
            float w = g_wgt[2 * t + k];
            const uint4* src = (const uint4*)(g_eo + ((size_t)e * CAP + s) * HDIM);
#pragma unroll
            for (int q = 0; q < 2; q++) {
                uint4 v = src[lane + q * 32];
                const __half2* h2 = (const __half2*)&v;
#pragma unroll
                for (int j = 0; j < 4; j++) {
                    float2 f = __half22float2(h2[j]);
                    acc[q * 8 + j * 2]     += w * f.x;
                    acc[q * 8 + j * 2 + 1] += w * f.y;
                }
            }
        }
    }
    float4* o = (float4*)(out + (size_t)t * HDIM);
#pragma unroll
    for (int q = 0; q < 2; q++) {
        o[(lane + q * 32) * 2] =
            make_float4(acc[q * 8 + 0], acc[q * 8 + 1], acc[q * 8 + 2], acc[q * 8 + 3]);
        o[(lane + q * 32) * 2 + 1] =
            make_float4(acc[q * 8 + 4], acc[q * 8 + 5], acc[q * 8 + 6], acc[q * 8 + 7]);
    }
}

// ---------------- launch -------------------------------------------------------
extern "C" void kernel_launch(void* const* d_in, const int* in_sizes, int n_in,
                              void* d_out, int out_size) {
    const float* x  = (const float*)d_in[0];
    const float* rw = (const float*)d_in[1];
    const float* w1 = (const float*)d_in[2];
    const float* b1 = (const float*)d_in[3];
    const float* w2 = (const float*)d_in[4];
    const float* b2 = (const float*)d_in[5];
    float* out = (float*)d_out;

    router_kernel<<<NTOK / 8, 256>>>(x, rw);
    assign_kernel<<<1, 1024>>>();
    tsplit_kernel<<<dim3(64, 16, 16), dim3(32, 8)>>>(w1, w2);
    moe_mma<true><<<dim3(FDIM / 128, CAP / 128, NEXP), 256>>>(b1);
    moe_mma<false><<<dim3(HDIM / 128, CAP / 128, NEXP), 256>>>(b2);
    combine_kernel<<<NTOK / 8, 256>>>(out);
}